// round 14
// baseline (speedup 1.0000x reference)
#include <cuda_runtime.h>
#include <cuda_fp16.h>
#include <stdint.h>
#include <math.h>

#define BB   32
#define TT   120
#define JJ   24
#define EE   128
#define HH   8
#define DH   16
#define DDIM 3072
#define FFD  256
#define NTOK (BB*TT)            // 3840
#define NEL  (NTOK*DDIM)        // 11,796,480
#define NROWCH 30
#define WELEM (HH*JJ*DH*EE)     // 393216

typedef __half fp16;

// ===================== PTX helpers =====================
__device__ __forceinline__ uint32_t smem_u32(const void* p) {
    uint32_t a;
    asm("{ .reg .u64 t; cvta.to.shared.u64 t, %1; cvt.u32.u64 %0, t; }" : "=r"(a) : "l"(p));
    return a;
}
__device__ __forceinline__ void ldmx4(uint32_t* r, uint32_t addr) {
    asm volatile("ldmatrix.sync.aligned.m8n8.x4.shared.b16 {%0,%1,%2,%3}, [%4];"
        : "=r"(r[0]), "=r"(r[1]), "=r"(r[2]), "=r"(r[3]) : "r"(addr));
}
__device__ __forceinline__ void mma16816(float* c, const uint32_t* a, uint32_t b0, uint32_t b1) {
    asm volatile("mma.sync.aligned.m16n8k16.row.col.f32.f16.f16.f32 "
        "{%0,%1,%2,%3}, {%4,%5,%6,%7}, {%8,%9}, {%0,%1,%2,%3};"
        : "+f"(c[0]), "+f"(c[1]), "+f"(c[2]), "+f"(c[3])
        : "r"(a[0]), "r"(a[1]), "r"(a[2]), "r"(a[3]), "r"(b0), "r"(b1));
}
__device__ __forceinline__ void cpa16(uint32_t saddr, const void* g) {
    asm volatile("cp.async.ca.shared.global [%0], [%1], 16;" :: "r"(saddr), "l"(g));
}
#define CPA_COMMIT() asm volatile("cp.async.commit_group;" ::: "memory")
#define CPA_WAIT0()  asm volatile("cp.async.wait_group 0;" ::: "memory")

// ===================== scratch (device globals) =====================
__device__ __align__(16) fp16  g_qkv_h[NTOK*JJ*384];
__device__ __align__(16) fp16  g_kv_h [NTOK*JJ*256];
__device__ __align__(16) fp16  g_q_h  [NEL];
__device__ __align__(16) fp16  g_ffn_h[NEL];
__device__ __align__(16) fp16  g_res1h[NEL];
__device__ __align__(16) fp16  g_res2h[NEL];
__device__ __align__(16) fp16  g_ffnp_h[4*NTOK*FFD];
__device__ __align__(16) fp16 g_src_h[NEL];
__device__ __align__(16) fp16 g_catT_h[NEL];
__device__ __align__(16) fp16 g_catS_h[NEL];
__device__ __align__(16) fp16 g_att_h[NEL];
__device__ __align__(16) fp16 g_h1_h[NTOK*FFD];
__device__ __align__(16) fp16 g_wqkv_t[JJ*384*EE];
__device__ __align__(16) fp16 g_wq_s[WELEM];
__device__ __align__(16) fp16 g_wkv_s[2*HH*DH*EE];
__device__ __align__(16) fp16 g_wpt_h[DDIM*DDIM];
__device__ __align__(16) fp16 g_wps_h[DDIM*DDIM];
__device__ __align__(16) fp16 g_w1_h[FFD*DDIM];
__device__ __align__(16) fp16 g_w2_h[DDIM*FFD];
__device__ float g_psS [2*NROWCH*DDIM];
__device__ float g_psS2[2*NROWCH*DDIM];
__device__ float g_mean[3*DDIM];
__device__ float g_var [3*DDIM];

// ===================== ONE merged prep kernel =====================
#define SEG0 ((long)NEL/4)
#define SEG1 ((long)DDIM*DDIM/4)
#define SEG2 ((long)DDIM*DDIM/4)
#define SEG3 ((long)FFD*DDIM/4)
#define SEG4 ((long)FFD*DDIM/4)
#define CVT_TOTAL (SEG0 + SEG1 + SEG2 + SEG3 + SEG4)
#define PREP_TOTAL (CVT_TOTAL + 2L*WELEM + (long)HH*DH*EE)
__global__ __launch_bounds__(256) void prep_all(
    const float* __restrict__ src,  fp16* __restrict__ src_h,
    const float* __restrict__ wpt,  fp16* __restrict__ wpt_h,
    const float* __restrict__ wps,  fp16* __restrict__ wps_h,
    const float* __restrict__ w1,   fp16* __restrict__ w1_h,
    const float* __restrict__ w2,   fp16* __restrict__ w2_h,
    const float* __restrict__ wq_t, const float* __restrict__ wk_t,
    const float* __restrict__ wv_t, fp16* __restrict__ wqkv_t,
    const float* __restrict__ wqs,  fp16* __restrict__ wq_s,
    const float* __restrict__ wks,  const float* __restrict__ wvs,
    fp16* __restrict__ wkv_s)
{
    long i = (long)blockIdx.x*256 + threadIdx.x;
    if (i >= PREP_TOTAL) return;
    if (i < CVT_TOTAL) {
        const float* in; fp16* o; long k;
        if      (i < SEG0)                  { in = src; o = src_h; k = i; }
        else if (i < SEG0+SEG1)             { in = wpt; o = wpt_h; k = i - SEG0; }
        else if (i < SEG0+SEG1+SEG2)        { in = wps; o = wps_h; k = i - SEG0 - SEG1; }
        else if (i < SEG0+SEG1+SEG2+SEG3)   { in = w1;  o = w1_h;  k = i - SEG0 - SEG1 - SEG2; }
        else                                { in = w2;  o = w2_h;  k = i - SEG0 - SEG1 - SEG2 - SEG3; }
        float4 x = ((const float4*)in)[k];
        ((__half2*)o)[2*k]   = __floats2half2_rn(x.x, x.y);
        ((__half2*)o)[2*k+1] = __floats2half2_rn(x.z, x.w);
        return;
    }
    long j = i - CVT_TOTAL;
    if (j < WELEM) {
        int idx = (int)j;
        int e  = idx & 127;
        int r  = idx >> 7;
        int dd = r & 15;
        int hj = r >> 4;
        int jj = hj % JJ;
        int h  = hj / JJ;
        int ob = jj*(384*128) + (h*16 + dd)*128 + e;
        wqkv_t[ob          ] = __float2half_rn(wq_t[idx]);
        wqkv_t[ob + 128*128] = __float2half_rn(wk_t[idx]);
        wqkv_t[ob + 256*128] = __float2half_rn(wv_t[idx]);
        return;
    }
    j -= WELEM;
    if (j < WELEM) {
        int idx = (int)j;
        int e  = idx & 127;
        int r  = idx >> 7;
        int dd = r & 15;
        int hj = r >> 4;
        int jj = hj % JJ;
        int h  = hj / JJ;
        wq_s[jj*16384 + (h*16 + dd)*128 + e] = __float2half_rn(wqs[idx]);
        return;
    }
    {
        int idx = (int)(j - WELEM);
        int n = HH*DH*EE;
        wkv_s[idx]     = __float2half_rn(wks[idx]);
        wkv_s[idx + n] = __float2half_rn(wvs[idx]);
    }
}

// ===================== GEMM body: CTA 128x128, 4 warps x (64x64), BK=64, 2-stage, XOR-swizzled ====
#define ABYTES 16384            // 128 rows x 128 bytes
#define BUFBYTES (2*ABYTES)     // 32768 per stage
#define TG_SMEM (2*BUFBYTES)    // 65536 -> 2 CTAs/SM (reg-bound)
template<bool STATS, bool OUTH, bool RESH>
__device__ __forceinline__ void gemm_body(
    const fp16* __restrict__ Ab, long lda,
    const fp16* __restrict__ Bb, long ldb,
    float* __restrict__ Cf, fp16* __restrict__ Ch, long ldc,
    const float* __restrict__ bias,
    const fp16* __restrict__ resh, long ldres,
    int K, int relu,
    float* __restrict__ psS, float* __restrict__ ps2S,
    char* dsm)
{
    const uint32_t sbase = smem_u32(dsm);
    const int tid = threadIdx.x;
    const int wid = tid >> 5, lid = tid & 31;
    const int wm = wid & 1, wn = wid >> 1;      // 2x2 warp grid, 64x64 each

    float acc[4][8][4];
    #pragma unroll
    for (int mt = 0; mt < 4; mt++)
        #pragma unroll
        for (int nt = 0; nt < 8; nt++)
            #pragma unroll
            for (int c = 0; c < 4; c++) acc[mt][nt][c] = 0.f;

    const int NC = K >> 6;
    const int row = tid >> 3;          // 0..15
    const int g   = tid & 7;
    // swizzled store offset: (r<<7) + ((g ^ (r&7))<<4); r&7 == row&7 for all i
    const uint32_t stoff = ((uint32_t)row << 7) + ((uint32_t)((g ^ (row & 7)) & 7) << 4);

    // prefetch chunk 0 -> buf 0
    {
        uint32_t sA0 = sbase, sB0 = sbase + ABYTES;
        #pragma unroll
        for (int i = 0; i < 8; i++) {
            int r = row + i*16;
            uint32_t s2 = stoff + (uint32_t)(i*2048);
            cpa16(sA0 + s2, Ab + (long)r*lda + g*8);
            cpa16(sB0 + s2, Bb + (long)r*ldb + g*8);
        }
        CPA_COMMIT();
    }

    const int fr  = lid & 15;
    const int hi  = lid >> 4;
    const int rx7 = fr & 7;

    for (int kc = 0; kc < NC; kc++) {
        const int b = kc & 1;
        CPA_WAIT0();
        __syncthreads();

        if (kc + 1 < NC) {
            uint32_t sA0 = sbase + (b^1)*BUFBYTES, sB0 = sA0 + ABYTES;
            long kof = (long)(kc + 1)*64;
            #pragma unroll
            for (int i = 0; i < 8; i++) {
                int r = row + i*16;
                uint32_t s2 = stoff + (uint32_t)(i*2048);
                cpa16(sA0 + s2, Ab + (long)r*lda + kof + g*8);
                cpa16(sB0 + s2, Bb + (long)r*ldb + kof + g*8);
            }
            CPA_COMMIT();
        }

        const uint32_t sA0 = sbase + b*BUFBYTES, sB0 = sA0 + ABYTES;
        #pragma unroll
        for (int kk = 0; kk < 4; kk++) {
            const uint32_t colg = (uint32_t)(((2*kk + hi) ^ rx7) << 4);
            uint32_t af[4][4];
            uint32_t bf[4][4];
            #pragma unroll
            for (int mt = 0; mt < 4; mt++)
                ldmx4(af[mt], sA0 + ((uint32_t)(wm*64 + mt*16 + fr) << 7) + colg);
            #pragma unroll
            for (int p = 0; p < 4; p++)
                ldmx4(bf[p], sB0 + ((uint32_t)(wn*64 + p*16 + fr) << 7) + colg);
            #pragma unroll
            for (int p = 0; p < 4; p++) {
                #pragma unroll
                for (int mt = 0; mt < 4; mt++) {
                    mma16816(acc[mt][2*p+0], af[mt], bf[p][0], bf[p][2]);
                    mma16816(acc[mt][2*p+1], af[mt], bf[p][1], bf[p][3]);
                }
            }
        }
    }

    // ---- epilogue ----
    const int qr = lid >> 2;
    const int qc = (lid & 3) * 2;
    float colS[16], colS2[16];
    if (STATS) {
        #pragma unroll
        for (int i = 0; i < 16; i++) { colS[i] = 0.f; colS2[i] = 0.f; }
    }
    #pragma unroll
    for (int mt = 0; mt < 4; mt++) {
        #pragma unroll
        for (int half = 0; half < 2; half++) {
            int m = wm*64 + mt*16 + half*8 + qr;
            #pragma unroll
            for (int nt = 0; nt < 8; nt++) {
                int n = wn*64 + nt*8 + qc;
                float v0 = acc[mt][nt][half*2+0];
                float v1 = acc[mt][nt][half*2+1];
                if (bias) { v0 += bias[n]; v1 += bias[n+1]; }
                if (RESH) {
                    __half2 rh = *(const __half2*)(resh + (long)m*ldres + n);
                    float2 rf = __half22float2(rh);
                    v0 += rf.x; v1 += rf.y;
                }
                if (relu) { v0 = fmaxf(v0, 0.f); v1 = fmaxf(v1, 0.f); }
                if (OUTH) {
                    *(__half2*)(Ch + (long)m*ldc + n) = __floats2half2_rn(v0, v1);
                } else {
                    float* Cp = Cf + (long)m*ldc + n;
                    Cp[0] = v0; Cp[1] = v1;
                }
                if (STATS) {
                    colS [nt*2+0] += v0; colS2[nt*2+0] += v0*v0;
                    colS [nt*2+1] += v1; colS2[nt*2+1] += v1*v1;
                }
            }
        }
    }
    if (STATS) {
        #pragma unroll
        for (int i = 0; i < 16; i++) {
            float s = colS[i], s2 = colS2[i];
            #pragma unroll
            for (int o = 4; o < 32; o <<= 1) {
                s  += __shfl_xor_sync(0xFFFFFFFFu, s,  o);
                s2 += __shfl_xor_sync(0xFFFFFFFFu, s2, o);
            }
            colS[i] = s; colS2[i] = s2;
        }
        __syncthreads();
        float* sred = (float*)dsm;   // [2 types][2 wm][128 cols]
        if (qr == 0) {
            int q2 = lid;  // 0..3
            #pragma unroll
            for (int i = 0; i < 16; i++) {
                int col = wn*64 + (i>>1)*8 + q2*2 + (i&1);
                sred[(0*2 + wm)*128 + col] = colS[i];
                sred[(1*2 + wm)*128 + col] = colS2[i];
            }
        }
        __syncthreads();
        #pragma unroll
        for (int rep = 0; rep < 2; rep++) {
            int s   = tid + rep*128;
            int ty  = s >> 7;
            int col = s & 127;
            float v = sred[(ty*2 + 0)*128 + col] + sred[(ty*2 + 1)*128 + col];
            if (ty == 0) psS[col] = v; else ps2S[col] = v;
        }
    }
}

// ---- merged QKV-type GEMMs: grid (6, 30, 24), 128 threads ----
__global__ __launch_bounds__(128, 2) void qkv_all(
    const fp16* __restrict__ src_h, const fp16* __restrict__ wqkv,
    const fp16* __restrict__ wqs, const fp16* __restrict__ wkvs,
    fp16* qkv_h, fp16* q_h, fp16* kv_h)
{
    extern __shared__ char dsm[];
    int bx = blockIdx.x, by = blockIdx.y, bz = blockIdx.z;
    const fp16 *A, *B; fp16* Ch; long lda, ldc;
    if (bx < 3) {
        A  = src_h + (long)bz*128 + (long)by*128*DDIM; lda = DDIM;
        B  = wqkv + (long)bz*(384*128) + (long)bx*128*128;
        Ch = qkv_h + (long)by*128*9216 + (long)bz*384 + bx*128; ldc = 9216;
    } else if (bx == 3) {
        A  = src_h + (long)bz*128 + (long)by*128*DDIM; lda = DDIM;
        B  = wqs + (long)bz*16384;
        Ch = q_h + (long)by*128*DDIM + (long)bz*128; ldc = DDIM;
    } else {
        long rt = (long)bz*30 + by;
        A  = src_h + rt*128*EE; lda = EE;
        B  = wkvs + (long)(bx-4)*128*EE;
        Ch = kv_h + rt*128*256 + (long)(bx-4)*128; ldc = 256;
    }
    gemm_body<false, true, false>(A, lda, B, EE, nullptr, Ch, ldc,
                                  nullptr, nullptr, 0, EE, 0, nullptr, nullptr, dsm);
}

// ---- merged projections (fp16 out + fp16 residual(src_h) + BN stats): grid (48, 30) ----
__global__ __launch_bounds__(128, 2) void proj_merged(
    const fp16* __restrict__ catT, const fp16* __restrict__ catS,
    const fp16* __restrict__ wpt, const fp16* __restrict__ wps,
    fp16* res1h, fp16* res2h,
    const float* __restrict__ bpt, const float* __restrict__ bps,
    const fp16* __restrict__ src_h,
    float* psS, float* psS2)
{
    extern __shared__ char dsm[];
    int bx = blockIdx.x, by = blockIdx.y;
    int sp = bx >= 24;
    int nx = sp ? bx - 24 : bx;
    const fp16* A = (sp ? catS : catT) + (long)by*128*DDIM;
    const fp16* B = (sp ? wps : wpt) + (long)nx*128*DDIM;
    fp16* C = (sp ? res2h : res1h) + (long)by*128*DDIM + nx*128;
    const float* bias = (sp ? bps : bpt) + nx*128;
    const fp16* resh = src_h + (long)by*128*DDIM + nx*128;
    float* pS  = psS  + (long)sp*NROWCH*DDIM + (long)by*DDIM + nx*128;
    float* pS2 = psS2 + (long)sp*NROWCH*DDIM + (long)by*DDIM + nx*128;
    gemm_body<true, true, true>(A, DDIM, B, DDIM, nullptr, C, DDIM,
                                bias, resh, DDIM, DDIM, 0, pS, pS2, dsm);
}

// ---- FFN1 split-K: grid (2, 30, 4), fp16 partials ----
__global__ __launch_bounds__(128, 2) void ffn1_gemm(
    const fp16* __restrict__ att_h, const fp16* __restrict__ w1, fp16* ffnp_h)
{
    extern __shared__ char dsm[];
    int bx = blockIdx.x, by = blockIdx.y, bz = blockIdx.z;
    const fp16* A = att_h + (long)bz*768 + (long)by*128*DDIM;
    const fp16* B = w1 + (long)bx*128*DDIM + (long)bz*768;
    fp16* C = ffnp_h + (long)bz*((long)NTOK*FFD) + (long)by*128*FFD + bx*128;
    gemm_body<false, true, false>(A, DDIM, B, DDIM, nullptr, C, FFD,
                                  nullptr, nullptr, 0, 768, 0, nullptr, nullptr, dsm);
}

// ---- FFN2 + bias + fp16 residual(att_h) + BN stats, fp16 out: grid (24, 30) ----
__global__ __launch_bounds__(128, 2) void ffn2_gemm(
    const fp16* __restrict__ h1, const fp16* __restrict__ w2,
    const float* __restrict__ b2, const fp16* __restrict__ att_h,
    fp16* ffn_h, float* psS, float* psS2)
{
    extern __shared__ char dsm[];
    int bx = blockIdx.x, by = blockIdx.y;
    const fp16* A = h1 + (long)by*128*FFD;
    const fp16* B = w2 + (long)bx*128*FFD;
    fp16* C = ffn_h + (long)by*128*DDIM + bx*128;
    const float* bias = b2 + bx*128;
    const fp16* resh = att_h + (long)by*128*DDIM + bx*128;
    float* pS  = psS  + (long)by*DDIM + bx*128;
    float* pS2 = psS2 + (long)by*DDIM + bx*128;
    gemm_body<true, true, true>(A, FFD, B, FFD, nullptr, C, DDIM,
                                bias, resh, DDIM, FFD, 0, pS, pS2, dsm);
}

// ===================== merged attention =====================
__global__ __launch_bounds__(256) void attn_all(
    const fp16* __restrict__ qkv, const fp16* __restrict__ q,
    const fp16* __restrict__ kv, fp16* __restrict__ oT, fp16* __restrict__ oS)
{
    __shared__ float sm[7680];
    int bi = blockIdx.x;
    if (bi < 3072) {
        int j = bi % 24, hp = (bi/24) & 3, b = bi / 96;
        int half = threadIdx.x >> 7;
        int tid = threadIdx.x & 127;
        int h = hp*2 + half;
        float* Ks = sm + half*(2*TT*DH);
        float* Vs = Ks + TT*DH;
        for (int idx = tid; idx < TT*DH; idx += 128) {
            int t = idx >> 4, dd = idx & 15;
            long off = (long)(b*TT + t)*9216 + j*384 + h*DH + dd;
            Ks[idx] = __half2float(qkv[off + 128]);
            Vs[idx] = __half2float(qkv[off + 256]);
        }
        __syncthreads();
        int t = tid;
        if (t < TT) {
            float qr[DH];
            long qoff = (long)(b*TT + t)*9216 + j*384 + h*DH;
            #pragma unroll
            for (int dd = 0; dd < DH; dd++) qr[dd] = __half2float(qkv[qoff + dd]);
            float m = -1e30f, l = 0.f, acc[DH];
            #pragma unroll
            for (int dd = 0; dd < DH; dd++) acc[dd] = 0.f;
            for (int s = 0; s <= t; s++) {
                float sc = 0.f;
                #pragma unroll
                for (int dd = 0; dd < DH; dd++) sc = fmaf(qr[dd], Ks[s*DH + dd], sc);
                sc *= 0.25f;
                float mn = fmaxf(m, sc);
                float corr = __expf(m - mn);
                float p    = __expf(sc - mn);
                l = l*corr + p;
                #pragma unroll
                for (int dd = 0; dd < DH; dd++) acc[dd] = fmaf(acc[dd], corr, p*Vs[s*DH + dd]);
                m = mn;
            }
            float inv = 1.f / l;
            long ooff = (long)(b*TT + t)*DDIM + h*(JJ*DH) + j*DH;
            #pragma unroll
            for (int dd = 0; dd < DH; dd++) oT[ooff + dd] = __float2half_rn(acc[dd]*inv);
        }
    } else {
        int tok  = bi - 3072;
        int h    = threadIdx.x >> 5;
        int lane = threadIdx.x & 31;
        float* Ks = sm;
        float* Vs = sm + HH*JJ*DH;
        for (int idx = lane; idx < JJ*DH; idx += 32) {
            int jj = idx >> 4, dd = idx & 15;
            long off = ((long)tok*JJ + jj)*256 + h*DH + dd;
            Ks[(h*JJ + jj)*DH + dd] = __half2float(kv[off]);
            Vs[(h*JJ + jj)*DH + dd] = __half2float(kv[off + 128]);
        }
        __syncwarp();
        if (lane < JJ) {
            int j = lane;
            float qr[DH];
            long qoff = (long)tok*DDIM + j*128 + h*DH;
            #pragma unroll
            for (int dd = 0; dd < DH; dd++) qr[dd] = __half2float(q[qoff + dd]);
            float s[JJ];
            float m = -1e30f;
            #pragma unroll
            for (int kk = 0; kk < JJ; kk++) {
                float sc = 0.f;
                #pragma unroll
                for (int dd = 0; dd < DH; dd++) sc = fmaf(qr[dd], Ks[(h*JJ + kk)*DH + dd], sc);
                sc *= 0.25f;
                s[kk] = sc;
                m = fmaxf(m, sc);
            }
            float l = 0.f;
            #pragma unroll
            for (int kk = 0; kk < JJ; kk++) { s[kk] = __expf(s[kk] - m); l += s[kk]; }
            float acc[DH];
            #pragma unroll
            for (int dd = 0; dd < DH; dd++) acc[dd] = 0.f;
            #pragma unroll
            for (int kk = 0; kk < JJ; kk++)
                #pragma unroll
                for (int dd = 0; dd < DH; dd++) acc[dd] = fmaf(s[kk], Vs[(h*JJ + kk)*DH + dd], acc[dd]);
            float inv = 1.f / l;
            long ooff = (long)tok*DDIM + h*(JJ*DH) + j*DH;
            #pragma unroll
            for (int dd = 0; dd < DH; dd++) oS[ooff + dd] = __float2half_rn(acc[dd]*inv);
        }
    }
}

// ===================== FFN1 split-K reduce (fp16 partials) =====================
__global__ __launch_bounds__(256) void ffn1_reduce(
    const fp16* __restrict__ p, const float* __restrict__ b1, fp16* __restrict__ oh)
{
    long i = (long)blockIdx.x*256 + threadIdx.x;      // over NTOK*FFD/8
    if (i >= (long)NTOK*FFD/8) return;
    const long stride = (long)NTOK*FFD/8;
    uint4 pa = ((const uint4*)p)[i];
    uint4 pb = ((const uint4*)p)[i + stride];
    uint4 pc = ((const uint4*)p)[i + 2*stride];
    uint4 pd = ((const uint4*)p)[i + 3*stride];
    int c0 = (int)((i*8) % FFD);
    uint32_t ra[4] = {pa.x, pa.y, pa.z, pa.w};
    uint32_t rb[4] = {pb.x, pb.y, pb.z, pb.w};
    uint32_t rc[4] = {pc.x, pc.y, pc.z, pc.w};
    uint32_t rd[4] = {pd.x, pd.y, pd.z, pd.w};
    uint32_t ro[4];
    #pragma unroll
    for (int k = 0; k < 4; k++) {
        float2 fa = __half22float2(*(__half2*)&ra[k]);
        float2 fb = __half22float2(*(__half2*)&rb[k]);
        float2 fc = __half22float2(*(__half2*)&rc[k]);
        float2 fd = __half22float2(*(__half2*)&rd[k]);
        float v0 = fmaxf(fa.x + fb.x + fc.x + fd.x + b1[c0 + 2*k],     0.f);
        float v1 = fmaxf(fa.y + fb.y + fc.y + fd.y + b1[c0 + 2*k + 1], 0.f);
        __half2 h = __floats2half2_rn(v0, v1);
        ro[k] = *(uint32_t*)&h;
    }
    ((uint4*)oh)[i] = make_uint4(ro[0], ro[1], ro[2], ro[3]);
}

// ===================== BN stage 2 =====================
__global__ __launch_bounds__(256) void bn_stats2(
    const float* __restrict__ ps, const float* __restrict__ ps2,
    float* __restrict__ mean, float* __restrict__ var)
{
    int c = blockIdx.x*256 + threadIdx.x;
    long base = (long)blockIdx.y*NROWCH*DDIM;
    float s = 0.f, s2 = 0.f;
    #pragma unroll
    for (int r = 0; r < NROWCH; r++) { s += ps[base + (long)r*DDIM + c]; s2 += ps2[base + (long)r*DDIM + c]; }
    float m = s / (float)NTOK;
    mean[blockIdx.y*DDIM + c] = m;
    var [blockIdx.y*DDIM + c] = s2 / (float)NTOK - m*m;
}

// att_h = bn_t(res1h) + bn_s(res2h)
__global__ __launch_bounds__(256) void combine_att(
    const fp16* __restrict__ x1, const fp16* __restrict__ x2,
    const float* __restrict__ gt, const float* __restrict__ bt,
    const float* __restrict__ gs, const float* __restrict__ bs,
    const float* __restrict__ mean, const float* __restrict__ var,
    fp16* __restrict__ oh)
{
    long i = (long)blockIdx.x*256 + threadIdx.x;
    if (i >= NEL/4) return;
    int c0 = (int)((i*4) % DDIM);
    float2 a01 = __half22float2(((const __half2*)x1)[2*i]);
    float2 a23 = __half22float2(((const __half2*)x1)[2*i+1]);
    float2 b01 = __half22float2(((const __half2*)x2)[2*i]);
    float2 b23 = __half22float2(((const __half2*)x2)[2*i+1]);
    float xa[4] = {a01.x, a01.y, a23.x, a23.y};
    float xb[4] = {b01.x, b01.y, b23.x, b23.y};
    float r[4];
    #pragma unroll
    for (int k = 0; k < 4; k++) {
        int c = c0 + k;
        float va = (xa[k] - mean[c])        * rsqrtf(var[c]        + 1e-5f) * gt[c] + bt[c];
        float vb = (xb[k] - mean[DDIM + c]) * rsqrtf(var[DDIM + c] + 1e-5f) * gs[c] + bs[c];
        r[k] = va + vb;
    }
    ((__half2*)oh)[2*i]   = __floats2half2_rn(r[0], r[1]);
    ((__half2*)oh)[2*i+1] = __floats2half2_rn(r[2], r[3]);
}

// final BN reads fp16 ffn
__global__ __launch_bounds__(256) void final_bn(
    const fp16* __restrict__ x,
    const float* __restrict__ gf, const float* __restrict__ bf,
    const float* __restrict__ mean, const float* __restrict__ var,
    float* __restrict__ out)
{
    long i = (long)blockIdx.x*256 + threadIdx.x;
    if (i >= NEL/4) return;
    int c0 = (int)((i*4) % DDIM);
    float2 a01 = __half22float2(((const __half2*)x)[2*i]);
    float2 a23 = __half22float2(((const __half2*)x)[2*i+1]);
    float xa[4] = {a01.x, a01.y, a23.x, a23.y};
    float r[4];
    #pragma unroll
    for (int k = 0; k < 4; k++) {
        int c = c0 + k;
        r[k] = (xa[k] - mean[c]) * rsqrtf(var[c] + 1e-5f) * gf[c] + bf[c];
    }
    ((float4*)out)[i] = make_float4(r[0], r[1], r[2], r[3]);
}

// ===================== launch =====================
extern "C" void kernel_launch(void* const* d_in, const int* in_sizes, int n_in,
                              void* d_out, int out_size)
{
    const float* src  = (const float*)d_in[0];
    const float* Wq_t = (const float*)d_in[1];
    const float* Wk_t = (const float*)d_in[2];
    const float* Wv_t = (const float*)d_in[3];
    const float* Wp_t = (const float*)d_in[4];
    const float* bp_t = (const float*)d_in[5];
    const float* g_t  = (const float*)d_in[6];
    const float* b_t  = (const float*)d_in[7];
    const float* Wq_s = (const float*)d_in[8];
    const float* Wk_s = (const float*)d_in[9];
    const float* Wv_s = (const float*)d_in[10];
    const float* Wp_s = (const float*)d_in[11];
    const float* bp_s = (const float*)d_in[12];
    const float* g_s  = (const float*)d_in[13];
    const float* b_s  = (const float*)d_in[14];
    const float* W1   = (const float*)d_in[15];
    const float* b1   = (const float*)d_in[16];
    const float* W2   = (const float*)d_in[17];
    const float* b2   = (const float*)d_in[18];
    const float* g_f  = (const float*)d_in[19];
    const float* b_f  = (const float*)d_in[20];
    float* out = (float*)d_out;

    float *psS,*psS2,*mean,*var;
    fp16 *qkv_h,*kv_h,*q_h,*ffn_h,*res1h,*res2h,*ffnp_h,*src_h,*catT_h,*catS_h,*att_h,*h1_h;
    fp16 *wqkv_t,*wq_s,*wkv_s,*wpt_h,*wps_h,*w1_h,*w2_h;
    cudaGetSymbolAddress((void**)&qkv_h,  g_qkv_h);
    cudaGetSymbolAddress((void**)&kv_h,   g_kv_h);
    cudaGetSymbolAddress((void**)&q_h,    g_q_h);
    cudaGetSymbolAddress((void**)&ffn_h,  g_ffn_h);
    cudaGetSymbolAddress((void**)&res1h,  g_res1h);
    cudaGetSymbolAddress((void**)&res2h,  g_res2h);
    cudaGetSymbolAddress((void**)&ffnp_h, g_ffnp_h);
    cudaGetSymbolAddress((void**)&psS,    g_psS);
    cudaGetSymbolAddress((void**)&psS2,   g_psS2);
    cudaGetSymbolAddress((void**)&mean,   g_mean);
    cudaGetSymbolAddress((void**)&var,    g_var);
    cudaGetSymbolAddress((void**)&src_h,  g_src_h);
    cudaGetSymbolAddress((void**)&catT_h, g_catT_h);
    cudaGetSymbolAddress((void**)&catS_h, g_catS_h);
    cudaGetSymbolAddress((void**)&att_h,  g_att_h);
    cudaGetSymbolAddress((void**)&h1_h,   g_h1_h);
    cudaGetSymbolAddress((void**)&wqkv_t, g_wqkv_t);
    cudaGetSymbolAddress((void**)&wq_s,   g_wq_s);
    cudaGetSymbolAddress((void**)&wkv_s,  g_wkv_s);
    cudaGetSymbolAddress((void**)&wpt_h,  g_wpt_h);
    cudaGetSymbolAddress((void**)&wps_h,  g_wps_h);
    cudaGetSymbolAddress((void**)&w1_h,   g_w1_h);
    cudaGetSymbolAddress((void**)&w2_h,   g_w2_h);

    cudaFuncSetAttribute(qkv_all,     cudaFuncAttributeMaxDynamicSharedMemorySize, TG_SMEM);
    cudaFuncSetAttribute(proj_merged, cudaFuncAttributeMaxDynamicSharedMemorySize, TG_SMEM);
    cudaFuncSetAttribute(ffn1_gemm,   cudaFuncAttributeMaxDynamicSharedMemorySize, TG_SMEM);
    cudaFuncSetAttribute(ffn2_gemm,   cudaFuncAttributeMaxDynamicSharedMemorySize, TG_SMEM);

    // ---- ONE prep launch ----
    prep_all<<<(int)((PREP_TOTAL + 255)/256), 256>>>(
        src, src_h, Wp_t, wpt_h, Wp_s, wps_h, W1, w1_h, W2, w2_h,
        Wq_t, Wk_t, Wv_t, wqkv_t, Wq_s, wq_s, Wk_s, Wv_s, wkv_s);

    // ---- all QKV-type GEMMs in one launch ----
    qkv_all<<<dim3(6, 30, 24), 128, TG_SMEM>>>(src_h, wqkv_t, wq_s, wkv_s, qkv_h, q_h, kv_h);

    // ---- both attentions in one launch ----
    attn_all<<<3072 + NTOK, 256>>>(qkv_h, q_h, kv_h, catT_h, catS_h);

    // ---- both projections (+bias +fp16 residual +BN stats, fp16 out) ----
    proj_merged<<<dim3(48, 30), 128, TG_SMEM>>>(catT_h, catS_h, wpt_h, wps_h,
                                                res1h, res2h, bp_t, bp_s, src_h, psS, psS2);

    // ---- BN stage2 for both branches ----
    bn_stats2<<<dim3(DDIM/256, 2), 256>>>(psS, psS2, mean, var);

    // ---- att_h = bn_t + bn_s ----
    combine_att<<<(NEL/4 + 255)/256, 256>>>(res1h, res2h, g_t, b_t, g_s, b_s,
                                            mean, var, att_h);

    // ---- FFN1 split-K=4 (fp16 partials) + reduce ----
    ffn1_gemm<<<dim3(2, 30, 4), 128, TG_SMEM>>>(att_h, w1_h, ffnp_h);
    ffn1_reduce<<<(int)(((long)NTOK*FFD/8 + 255)/256), 256>>>(ffnp_h, b1, h1_h);

    // ---- FFN2 (+bias +fp16 residual +BN stats, fp16 out) ----
    ffn2_gemm<<<dim3(24, 30), 128, TG_SMEM>>>(h1_h, w2_h, b2, att_h, ffn_h, psS, psS2);

    // ---- final BN ----
    bn_stats2<<<dim3(DDIM/256, 1), 256>>>(psS, psS2, mean + 2*DDIM, var + 2*DDIM);
    final_bn<<<(NEL/4 + 255)/256, 256>>>(ffn_h, g_f, b_f, mean + 2*DDIM, var + 2*DDIM, out);
}

// round 15
// speedup vs baseline: 1.0367x; 1.0367x over previous
#include <cuda_runtime.h>
#include <cuda_fp16.h>
#include <stdint.h>
#include <math.h>

#define BB   32
#define TT   120
#define JJ   24
#define EE   128
#define HH   8
#define DH   16
#define DDIM 3072
#define FFD  256
#define NTOK (BB*TT)            // 3840
#define NEL  (NTOK*DDIM)        // 11,796,480
#define NROWCH 30
#define WELEM (HH*JJ*DH*EE)     // 393216

typedef __half fp16;

// ===================== PTX helpers =====================
__device__ __forceinline__ uint32_t smem_u32(const void* p) {
    uint32_t a;
    asm("{ .reg .u64 t; cvta.to.shared.u64 t, %1; cvt.u32.u64 %0, t; }" : "=r"(a) : "l"(p));
    return a;
}
__device__ __forceinline__ void ldmx4(uint32_t* r, uint32_t addr) {
    asm volatile("ldmatrix.sync.aligned.m8n8.x4.shared.b16 {%0,%1,%2,%3}, [%4];"
        : "=r"(r[0]), "=r"(r[1]), "=r"(r[2]), "=r"(r[3]) : "r"(addr));
}
__device__ __forceinline__ void mma16816(float* c, const uint32_t* a, uint32_t b0, uint32_t b1) {
    asm volatile("mma.sync.aligned.m16n8k16.row.col.f32.f16.f16.f32 "
        "{%0,%1,%2,%3}, {%4,%5,%6,%7}, {%8,%9}, {%0,%1,%2,%3};"
        : "+f"(c[0]), "+f"(c[1]), "+f"(c[2]), "+f"(c[3])
        : "r"(a[0]), "r"(a[1]), "r"(a[2]), "r"(a[3]), "r"(b0), "r"(b1));
}
__device__ __forceinline__ void cpa16(uint32_t saddr, const void* g) {
    asm volatile("cp.async.ca.shared.global [%0], [%1], 16;" :: "r"(saddr), "l"(g));
}
#define CPA_COMMIT() asm volatile("cp.async.commit_group;" ::: "memory")
#define CPA_WAIT0()  asm volatile("cp.async.wait_group 0;" ::: "memory")

// ===================== scratch (device globals) =====================
__device__ __align__(16) fp16  g_qkv_h[NTOK*JJ*384];
__device__ __align__(16) fp16  g_kv_h [NTOK*JJ*256];
__device__ __align__(16) fp16  g_q_h  [NEL];
__device__ __align__(16) fp16  g_ffn_h[NEL];
__device__ __align__(16) fp16  g_res1h[NEL];
__device__ __align__(16) fp16  g_res2h[NEL];
__device__ __align__(16) fp16  g_ffnp_h[4*NTOK*FFD];
__device__ __align__(16) fp16 g_src_h[NEL];
__device__ __align__(16) fp16 g_catT_h[NEL];
__device__ __align__(16) fp16 g_catS_h[NEL];
__device__ __align__(16) fp16 g_att_h[NEL];
__device__ __align__(16) fp16 g_h1_h[NTOK*FFD];
__device__ __align__(16) fp16 g_wqkv_t[JJ*384*EE];
__device__ __align__(16) fp16 g_wq_s[WELEM];
__device__ __align__(16) fp16 g_wkv_s[2*HH*DH*EE];
__device__ __align__(16) fp16 g_wpt_h[DDIM*DDIM];
__device__ __align__(16) fp16 g_wps_h[DDIM*DDIM];
__device__ __align__(16) fp16 g_w1_h[FFD*DDIM];
__device__ __align__(16) fp16 g_w2_h[DDIM*FFD];
__device__ float g_psS [2*NROWCH*DDIM];
__device__ float g_psS2[2*NROWCH*DDIM];
__device__ float g_mean[3*DDIM];
__device__ float g_var [3*DDIM];

// ===================== ONE merged prep kernel =====================
#define SEG0 ((long)NEL/4)
#define SEG1 ((long)DDIM*DDIM/4)
#define SEG2 ((long)DDIM*DDIM/4)
#define SEG3 ((long)FFD*DDIM/4)
#define SEG4 ((long)FFD*DDIM/4)
#define CVT_TOTAL (SEG0 + SEG1 + SEG2 + SEG3 + SEG4)
#define PREP_TOTAL (CVT_TOTAL + 2L*WELEM + (long)HH*DH*EE)
__global__ __launch_bounds__(256) void prep_all(
    const float* __restrict__ src,  fp16* __restrict__ src_h,
    const float* __restrict__ wpt,  fp16* __restrict__ wpt_h,
    const float* __restrict__ wps,  fp16* __restrict__ wps_h,
    const float* __restrict__ w1,   fp16* __restrict__ w1_h,
    const float* __restrict__ w2,   fp16* __restrict__ w2_h,
    const float* __restrict__ wq_t, const float* __restrict__ wk_t,
    const float* __restrict__ wv_t, fp16* __restrict__ wqkv_t,
    const float* __restrict__ wqs,  fp16* __restrict__ wq_s,
    const float* __restrict__ wks,  const float* __restrict__ wvs,
    fp16* __restrict__ wkv_s)
{
    long i = (long)blockIdx.x*256 + threadIdx.x;
    if (i >= PREP_TOTAL) return;
    if (i < CVT_TOTAL) {
        const float* in; fp16* o; long k;
        if      (i < SEG0)                  { in = src; o = src_h; k = i; }
        else if (i < SEG0+SEG1)             { in = wpt; o = wpt_h; k = i - SEG0; }
        else if (i < SEG0+SEG1+SEG2)        { in = wps; o = wps_h; k = i - SEG0 - SEG1; }
        else if (i < SEG0+SEG1+SEG2+SEG3)   { in = w1;  o = w1_h;  k = i - SEG0 - SEG1 - SEG2; }
        else                                { in = w2;  o = w2_h;  k = i - SEG0 - SEG1 - SEG2 - SEG3; }
        float4 x = ((const float4*)in)[k];
        ((__half2*)o)[2*k]   = __floats2half2_rn(x.x, x.y);
        ((__half2*)o)[2*k+1] = __floats2half2_rn(x.z, x.w);
        return;
    }
    long j = i - CVT_TOTAL;
    if (j < WELEM) {
        int idx = (int)j;
        int e  = idx & 127;
        int r  = idx >> 7;
        int dd = r & 15;
        int hj = r >> 4;
        int jj = hj % JJ;
        int h  = hj / JJ;
        int ob = jj*(384*128) + (h*16 + dd)*128 + e;
        wqkv_t[ob          ] = __float2half_rn(wq_t[idx]);
        wqkv_t[ob + 128*128] = __float2half_rn(wk_t[idx]);
        wqkv_t[ob + 256*128] = __float2half_rn(wv_t[idx]);
        return;
    }
    j -= WELEM;
    if (j < WELEM) {
        int idx = (int)j;
        int e  = idx & 127;
        int r  = idx >> 7;
        int dd = r & 15;
        int hj = r >> 4;
        int jj = hj % JJ;
        int h  = hj / JJ;
        wq_s[jj*16384 + (h*16 + dd)*128 + e] = __float2half_rn(wqs[idx]);
        return;
    }
    {
        int idx = (int)(j - WELEM);
        int n = HH*DH*EE;
        wkv_s[idx]     = __float2half_rn(wks[idx]);
        wkv_s[idx + n] = __float2half_rn(wvs[idx]);
    }
}

// ===================== GEMM body: CTA 128x128, 4 warps x (64x64), BK=64, 2-stage =====================
#define ROWB 144
#define ABYTES (128*ROWB)
#define BUFBYTES (2*ABYTES)   // 36864 per stage
#define TG_SMEM (2*BUFBYTES)  // 73728 -> 2 CTAs/SM
template<bool STATS, bool OUTH, bool RESH>
__device__ __forceinline__ void gemm_body(
    const fp16* __restrict__ Ab, long lda,
    const fp16* __restrict__ Bb, long ldb,
    float* __restrict__ Cf, fp16* __restrict__ Ch, long ldc,
    const float* __restrict__ bias,
    const fp16* __restrict__ resh, long ldres,
    int K, int relu,
    float* __restrict__ psS, float* __restrict__ ps2S,
    char* dsm)
{
    const uint32_t sbase = smem_u32(dsm);
    const int tid = threadIdx.x;
    const int wid = tid >> 5, lid = tid & 31;
    const int wm = wid & 1, wn = wid >> 1;      // 2x2 warp grid, 64x64 each

    float acc[4][8][4];
    #pragma unroll
    for (int mt = 0; mt < 4; mt++)
        #pragma unroll
        for (int nt = 0; nt < 8; nt++)
            #pragma unroll
            for (int c = 0; c < 4; c++) acc[mt][nt][c] = 0.f;

    const int NC = K >> 6;
    const int row = tid >> 3;          // 0..15
    const int g   = tid & 7;
    const uint32_t so = (uint32_t)(row*ROWB + g*16);

    // prefetch chunk 0 -> buf 0
    {
        uint32_t sA0 = sbase, sB0 = sbase + ABYTES;
        #pragma unroll
        for (int i = 0; i < 8; i++) {
            int r = row + i*16;
            uint32_t s2 = so + (uint32_t)(i*16*ROWB);
            cpa16(sA0 + s2, Ab + (long)r*lda + g*8);
            cpa16(sB0 + s2, Bb + (long)r*ldb + g*8);
        }
        CPA_COMMIT();
    }

    for (int kc = 0; kc < NC; kc++) {
        const int b = kc & 1;
        CPA_WAIT0();
        __syncthreads();

        if (kc + 1 < NC) {
            uint32_t sA0 = sbase + (b^1)*BUFBYTES, sB0 = sA0 + ABYTES;
            long kof = (long)(kc + 1)*64;
            #pragma unroll
            for (int i = 0; i < 8; i++) {
                int r = row + i*16;
                uint32_t s2 = so + (uint32_t)(i*16*ROWB);
                cpa16(sA0 + s2, Ab + (long)r*lda + kof + g*8);
                cpa16(sB0 + s2, Bb + (long)r*ldb + kof + g*8);
            }
            CPA_COMMIT();
        }

        const uint32_t sA0 = sbase + b*BUFBYTES, sB0 = sA0 + ABYTES;
        const int fr = lid & 15;
        #pragma unroll
        for (int kk = 0; kk < 4; kk++) {
            const uint32_t fcb = (uint32_t)((kk*16 + (lid >> 4)*8) * 2);
            uint32_t af[4][4];
            uint32_t bf[4][4];
            // batch ALL fragment loads up front: 8 LDSM in flight, then 32 MMAs unbroken
            #pragma unroll
            for (int mt = 0; mt < 4; mt++)
                ldmx4(af[mt], sA0 + (uint32_t)((wm*64 + mt*16 + fr)*ROWB) + fcb);
            #pragma unroll
            for (int p = 0; p < 4; p++)
                ldmx4(bf[p], sB0 + (uint32_t)((wn*64 + p*16 + fr)*ROWB) + fcb);
            #pragma unroll
            for (int p = 0; p < 4; p++) {
                #pragma unroll
                for (int mt = 0; mt < 4; mt++) {
                    mma16816(acc[mt][2*p+0], af[mt], bf[p][0], bf[p][2]);
                    mma16816(acc[mt][2*p+1], af[mt], bf[p][1], bf[p][3]);
                }
            }
        }
    }

    // ---- epilogue ----
    const int qr = lid >> 2;
    const int qc = (lid & 3) * 2;
    float colS[16], colS2[16];
    if (STATS) {
        #pragma unroll
        for (int i = 0; i < 16; i++) { colS[i] = 0.f; colS2[i] = 0.f; }
    }
    #pragma unroll
    for (int mt = 0; mt < 4; mt++) {
        #pragma unroll
        for (int half = 0; half < 2; half++) {
            int m = wm*64 + mt*16 + half*8 + qr;
            #pragma unroll
            for (int nt = 0; nt < 8; nt++) {
                int n = wn*64 + nt*8 + qc;
                float v0 = acc[mt][nt][half*2+0];
                float v1 = acc[mt][nt][half*2+1];
                if (bias) { v0 += bias[n]; v1 += bias[n+1]; }
                if (RESH) {
                    __half2 rh = *(const __half2*)(resh + (long)m*ldres + n);
                    float2 rf = __half22float2(rh);
                    v0 += rf.x; v1 += rf.y;
                }
                if (relu) { v0 = fmaxf(v0, 0.f); v1 = fmaxf(v1, 0.f); }
                if (OUTH) {
                    *(__half2*)(Ch + (long)m*ldc + n) = __floats2half2_rn(v0, v1);
                } else {
                    float* Cp = Cf + (long)m*ldc + n;
                    Cp[0] = v0; Cp[1] = v1;
                }
                if (STATS) {
                    colS [nt*2+0] += v0; colS2[nt*2+0] += v0*v0;
                    colS [nt*2+1] += v1; colS2[nt*2+1] += v1*v1;
                }
            }
        }
    }
    if (STATS) {
        #pragma unroll
        for (int i = 0; i < 16; i++) {
            float s = colS[i], s2 = colS2[i];
            #pragma unroll
            for (int o = 4; o < 32; o <<= 1) {
                s  += __shfl_xor_sync(0xFFFFFFFFu, s,  o);
                s2 += __shfl_xor_sync(0xFFFFFFFFu, s2, o);
            }
            colS[i] = s; colS2[i] = s2;
        }
        __syncthreads();
        float* sred = (float*)dsm;   // [2 types][2 wm][128 cols]
        if (qr == 0) {
            int q2 = lid;  // 0..3
            #pragma unroll
            for (int i = 0; i < 16; i++) {
                int col = wn*64 + (i>>1)*8 + q2*2 + (i&1);
                sred[(0*2 + wm)*128 + col] = colS[i];
                sred[(1*2 + wm)*128 + col] = colS2[i];
            }
        }
        __syncthreads();
        #pragma unroll
        for (int rep = 0; rep < 2; rep++) {
            int s   = tid + rep*128;
            int ty  = s >> 7;
            int col = s & 127;
            float v = sred[(ty*2 + 0)*128 + col] + sred[(ty*2 + 1)*128 + col];
            if (ty == 0) psS[col] = v; else ps2S[col] = v;
        }
    }
}

// ---- merged QKV-type GEMMs: grid (6, 30, 24), 128 threads ----
__global__ __launch_bounds__(128, 2) void qkv_all(
    const fp16* __restrict__ src_h, const fp16* __restrict__ wqkv,
    const fp16* __restrict__ wqs, const fp16* __restrict__ wkvs,
    fp16* qkv_h, fp16* q_h, fp16* kv_h)
{
    extern __shared__ char dsm[];
    int bx = blockIdx.x, by = blockIdx.y, bz = blockIdx.z;
    const fp16 *A, *B; fp16* Ch; long lda, ldc;
    if (bx < 3) {
        A  = src_h + (long)bz*128 + (long)by*128*DDIM; lda = DDIM;
        B  = wqkv + (long)bz*(384*128) + (long)bx*128*128;
        Ch = qkv_h + (long)by*128*9216 + (long)bz*384 + bx*128; ldc = 9216;
    } else if (bx == 3) {
        A  = src_h + (long)bz*128 + (long)by*128*DDIM; lda = DDIM;
        B  = wqs + (long)bz*16384;
        Ch = q_h + (long)by*128*DDIM + (long)bz*128; ldc = DDIM;
    } else {
        long rt = (long)bz*30 + by;
        A  = src_h + rt*128*EE; lda = EE;
        B  = wkvs + (long)(bx-4)*128*EE;
        Ch = kv_h + rt*128*256 + (long)(bx-4)*128; ldc = 256;
    }
    gemm_body<false, true, false>(A, lda, B, EE, nullptr, Ch, ldc,
                                  nullptr, nullptr, 0, EE, 0, nullptr, nullptr, dsm);
}

// ---- merged projections (fp16 out + fp16 residual(src_h) + BN stats): grid (48, 30) ----
__global__ __launch_bounds__(128, 2) void proj_merged(
    const fp16* __restrict__ catT, const fp16* __restrict__ catS,
    const fp16* __restrict__ wpt, const fp16* __restrict__ wps,
    fp16* res1h, fp16* res2h,
    const float* __restrict__ bpt, const float* __restrict__ bps,
    const fp16* __restrict__ src_h,
    float* psS, float* psS2)
{
    extern __shared__ char dsm[];
    int bx = blockIdx.x, by = blockIdx.y;
    int sp = bx >= 24;
    int nx = sp ? bx - 24 : bx;
    const fp16* A = (sp ? catS : catT) + (long)by*128*DDIM;
    const fp16* B = (sp ? wps : wpt) + (long)nx*128*DDIM;
    fp16* C = (sp ? res2h : res1h) + (long)by*128*DDIM + nx*128;
    const float* bias = (sp ? bps : bpt) + nx*128;
    const fp16* resh = src_h + (long)by*128*DDIM + nx*128;
    float* pS  = psS  + (long)sp*NROWCH*DDIM + (long)by*DDIM + nx*128;
    float* pS2 = psS2 + (long)sp*NROWCH*DDIM + (long)by*DDIM + nx*128;
    gemm_body<true, true, true>(A, DDIM, B, DDIM, nullptr, C, DDIM,
                                bias, resh, DDIM, DDIM, 0, pS, pS2, dsm);
}

// ---- FFN1 split-K: grid (2, 30, 4), fp16 partials ----
__global__ __launch_bounds__(128, 2) void ffn1_gemm(
    const fp16* __restrict__ att_h, const fp16* __restrict__ w1, fp16* ffnp_h)
{
    extern __shared__ char dsm[];
    int bx = blockIdx.x, by = blockIdx.y, bz = blockIdx.z;
    const fp16* A = att_h + (long)bz*768 + (long)by*128*DDIM;
    const fp16* B = w1 + (long)bx*128*DDIM + (long)bz*768;
    fp16* C = ffnp_h + (long)bz*((long)NTOK*FFD) + (long)by*128*FFD + bx*128;
    gemm_body<false, true, false>(A, DDIM, B, DDIM, nullptr, C, FFD,
                                  nullptr, nullptr, 0, 768, 0, nullptr, nullptr, dsm);
}

// ---- FFN2 + bias + fp16 residual(att_h) + BN stats, fp16 out: grid (24, 30) ----
__global__ __launch_bounds__(128, 2) void ffn2_gemm(
    const fp16* __restrict__ h1, const fp16* __restrict__ w2,
    const float* __restrict__ b2, const fp16* __restrict__ att_h,
    fp16* ffn_h, float* psS, float* psS2)
{
    extern __shared__ char dsm[];
    int bx = blockIdx.x, by = blockIdx.y;
    const fp16* A = h1 + (long)by*128*FFD;
    const fp16* B = w2 + (long)bx*128*FFD;
    fp16* C = ffn_h + (long)by*128*DDIM + bx*128;
    const float* bias = b2 + bx*128;
    const fp16* resh = att_h + (long)by*128*DDIM + bx*128;
    float* pS  = psS  + (long)by*DDIM + bx*128;
    float* pS2 = psS2 + (long)by*DDIM + bx*128;
    gemm_body<true, true, true>(A, FFD, B, FFD, nullptr, C, DDIM,
                                bias, resh, DDIM, FFD, 0, pS, pS2, dsm);
}

// ===================== merged attention =====================
__global__ __launch_bounds__(256) void attn_all(
    const fp16* __restrict__ qkv, const fp16* __restrict__ q,
    const fp16* __restrict__ kv, fp16* __restrict__ oT, fp16* __restrict__ oS)
{
    __shared__ float sm[7680];
    int bi = blockIdx.x;
    if (bi < 3072) {
        int j = bi % 24, hp = (bi/24) & 3, b = bi / 96;
        int half = threadIdx.x >> 7;
        int tid = threadIdx.x & 127;
        int h = hp*2 + half;
        float* Ks = sm + half*(2*TT*DH);
        float* Vs = Ks + TT*DH;
        for (int idx = tid; idx < TT*DH; idx += 128) {
            int t = idx >> 4, dd = idx & 15;
            long off = (long)(b*TT + t)*9216 + j*384 + h*DH + dd;
            Ks[idx] = __half2float(qkv[off + 128]);
            Vs[idx] = __half2float(qkv[off + 256]);
        }
        __syncthreads();
        int t = tid;
        if (t < TT) {
            float qr[DH];
            long qoff = (long)(b*TT + t)*9216 + j*384 + h*DH;
            #pragma unroll
            for (int dd = 0; dd < DH; dd++) qr[dd] = __half2float(qkv[qoff + dd]);
            float m = -1e30f, l = 0.f, acc[DH];
            #pragma unroll
            for (int dd = 0; dd < DH; dd++) acc[dd] = 0.f;
            for (int s = 0; s <= t; s++) {
                float sc = 0.f;
                #pragma unroll
                for (int dd = 0; dd < DH; dd++) sc = fmaf(qr[dd], Ks[s*DH + dd], sc);
                sc *= 0.25f;
                float mn = fmaxf(m, sc);
                float corr = __expf(m - mn);
                float p    = __expf(sc - mn);
                l = l*corr + p;
                #pragma unroll
                for (int dd = 0; dd < DH; dd++) acc[dd] = fmaf(acc[dd], corr, p*Vs[s*DH + dd]);
                m = mn;
            }
            float inv = 1.f / l;
            long ooff = (long)(b*TT + t)*DDIM + h*(JJ*DH) + j*DH;
            #pragma unroll
            for (int dd = 0; dd < DH; dd++) oT[ooff + dd] = __float2half_rn(acc[dd]*inv);
        }
    } else {
        int tok  = bi - 3072;
        int h    = threadIdx.x >> 5;
        int lane = threadIdx.x & 31;
        float* Ks = sm;
        float* Vs = sm + HH*JJ*DH;
        for (int idx = lane; idx < JJ*DH; idx += 32) {
            int jj = idx >> 4, dd = idx & 15;
            long off = ((long)tok*JJ + jj)*256 + h*DH + dd;
            Ks[(h*JJ + jj)*DH + dd] = __half2float(kv[off]);
            Vs[(h*JJ + jj)*DH + dd] = __half2float(kv[off + 128]);
        }
        __syncwarp();
        if (lane < JJ) {
            int j = lane;
            float qr[DH];
            long qoff = (long)tok*DDIM + j*128 + h*DH;
            #pragma unroll
            for (int dd = 0; dd < DH; dd++) qr[dd] = __half2float(q[qoff + dd]);
            float s[JJ];
            float m = -1e30f;
            #pragma unroll
            for (int kk = 0; kk < JJ; kk++) {
                float sc = 0.f;
                #pragma unroll
                for (int dd = 0; dd < DH; dd++) sc = fmaf(qr[dd], Ks[(h*JJ + kk)*DH + dd], sc);
                sc *= 0.25f;
                s[kk] = sc;
                m = fmaxf(m, sc);
            }
            float l = 0.f;
            #pragma unroll
            for (int kk = 0; kk < JJ; kk++) { s[kk] = __expf(s[kk] - m); l += s[kk]; }
            float acc[DH];
            #pragma unroll
            for (int dd = 0; dd < DH; dd++) acc[dd] = 0.f;
            #pragma unroll
            for (int kk = 0; kk < JJ; kk++)
                #pragma unroll
                for (int dd = 0; dd < DH; dd++) acc[dd] = fmaf(s[kk], Vs[(h*JJ + kk)*DH + dd], acc[dd]);
            float inv = 1.f / l;
            long ooff = (long)tok*DDIM + h*(JJ*DH) + j*DH;
            #pragma unroll
            for (int dd = 0; dd < DH; dd++) oS[ooff + dd] = __float2half_rn(acc[dd]*inv);
        }
    }
}

// ===================== FFN1 split-K reduce (fp16 partials) =====================
__global__ __launch_bounds__(256) void ffn1_reduce(
    const fp16* __restrict__ p, const float* __restrict__ b1, fp16* __restrict__ oh)
{
    long i = (long)blockIdx.x*256 + threadIdx.x;      // over NTOK*FFD/8
    if (i >= (long)NTOK*FFD/8) return;
    const long stride = (long)NTOK*FFD/8;
    uint4 pa = ((const uint4*)p)[i];
    uint4 pb = ((const uint4*)p)[i + stride];
    uint4 pc = ((const uint4*)p)[i + 2*stride];
    uint4 pd = ((const uint4*)p)[i + 3*stride];
    int c0 = (int)((i*8) % FFD);
    uint32_t ra[4] = {pa.x, pa.y, pa.z, pa.w};
    uint32_t rb[4] = {pb.x, pb.y, pb.z, pb.w};
    uint32_t rc[4] = {pc.x, pc.y, pc.z, pc.w};
    uint32_t rd[4] = {pd.x, pd.y, pd.z, pd.w};
    uint32_t ro[4];
    #pragma unroll
    for (int k = 0; k < 4; k++) {
        float2 fa = __half22float2(*(__half2*)&ra[k]);
        float2 fb = __half22float2(*(__half2*)&rb[k]);
        float2 fc = __half22float2(*(__half2*)&rc[k]);
        float2 fd = __half22float2(*(__half2*)&rd[k]);
        float v0 = fmaxf(fa.x + fb.x + fc.x + fd.x + b1[c0 + 2*k],     0.f);
        float v1 = fmaxf(fa.y + fb.y + fc.y + fd.y + b1[c0 + 2*k + 1], 0.f);
        __half2 h = __floats2half2_rn(v0, v1);
        ro[k] = *(uint32_t*)&h;
    }
    ((uint4*)oh)[i] = make_uint4(ro[0], ro[1], ro[2], ro[3]);
}

// ===================== BN stage 2 =====================
__global__ __launch_bounds__(256) void bn_stats2(
    const float* __restrict__ ps, const float* __restrict__ ps2,
    float* __restrict__ mean, float* __restrict__ var)
{
    int c = blockIdx.x*256 + threadIdx.x;
    long base = (long)blockIdx.y*NROWCH*DDIM;
    float s = 0.f, s2 = 0.f;
    #pragma unroll
    for (int r = 0; r < NROWCH; r++) { s += ps[base + (long)r*DDIM + c]; s2 += ps2[base + (long)r*DDIM + c]; }
    float m = s / (float)NTOK;
    mean[blockIdx.y*DDIM + c] = m;
    var [blockIdx.y*DDIM + c] = s2 / (float)NTOK - m*m;
}

// att_h = bn_t(res1h) + bn_s(res2h)
__global__ __launch_bounds__(256) void combine_att(
    const fp16* __restrict__ x1, const fp16* __restrict__ x2,
    const float* __restrict__ gt, const float* __restrict__ bt,
    const float* __restrict__ gs, const float* __restrict__ bs,
    const float* __restrict__ mean, const float* __restrict__ var,
    fp16* __restrict__ oh)
{
    long i = (long)blockIdx.x*256 + threadIdx.x;
    if (i >= NEL/4) return;
    int c0 = (int)((i*4) % DDIM);
    float2 a01 = __half22float2(((const __half2*)x1)[2*i]);
    float2 a23 = __half22float2(((const __half2*)x1)[2*i+1]);
    float2 b01 = __half22float2(((const __half2*)x2)[2*i]);
    float2 b23 = __half22float2(((const __half2*)x2)[2*i+1]);
    float xa[4] = {a01.x, a01.y, a23.x, a23.y};
    float xb[4] = {b01.x, b01.y, b23.x, b23.y};
    float r[4];
    #pragma unroll
    for (int k = 0; k < 4; k++) {
        int c = c0 + k;
        float va = (xa[k] - mean[c])        * rsqrtf(var[c]        + 1e-5f) * gt[c] + bt[c];
        float vb = (xb[k] - mean[DDIM + c]) * rsqrtf(var[DDIM + c] + 1e-5f) * gs[c] + bs[c];
        r[k] = va + vb;
    }
    ((__half2*)oh)[2*i]   = __floats2half2_rn(r[0], r[1]);
    ((__half2*)oh)[2*i+1] = __floats2half2_rn(r[2], r[3]);
}

// final BN reads fp16 ffn
__global__ __launch_bounds__(256) void final_bn(
    const fp16* __restrict__ x,
    const float* __restrict__ gf, const float* __restrict__ bf,
    const float* __restrict__ mean, const float* __restrict__ var,
    float* __restrict__ out)
{
    long i = (long)blockIdx.x*256 + threadIdx.x;
    if (i >= NEL/4) return;
    int c0 = (int)((i*4) % DDIM);
    float2 a01 = __half22float2(((const __half2*)x)[2*i]);
    float2 a23 = __half22float2(((const __half2*)x)[2*i+1]);
    float xa[4] = {a01.x, a01.y, a23.x, a23.y};
    float r[4];
    #pragma unroll
    for (int k = 0; k < 4; k++) {
        int c = c0 + k;
        r[k] = (xa[k] - mean[c]) * rsqrtf(var[c] + 1e-5f) * gf[c] + bf[c];
    }
    ((float4*)out)[i] = make_float4(r[0], r[1], r[2], r[3]);
}

// ===================== launch =====================
extern "C" void kernel_launch(void* const* d_in, const int* in_sizes, int n_in,
                              void* d_out, int out_size)
{
    const float* src  = (const float*)d_in[0];
    const float* Wq_t = (const float*)d_in[1];
    const float* Wk_t = (const float*)d_in[2];
    const float* Wv_t = (const float*)d_in[3];
    const float* Wp_t = (const float*)d_in[4];
    const float* bp_t = (const float*)d_in[5];
    const float* g_t  = (const float*)d_in[6];
    const float* b_t  = (const float*)d_in[7];
    const float* Wq_s = (const float*)d_in[8];
    const float* Wk_s = (const float*)d_in[9];
    const float* Wv_s = (const float*)d_in[10];
    const float* Wp_s = (const float*)d_in[11];
    const float* bp_s = (const float*)d_in[12];
    const float* g_s  = (const float*)d_in[13];
    const float* b_s  = (const float*)d_in[14];
    const float* W1   = (const float*)d_in[15];
    const float* b1   = (const float*)d_in[16];
    const float* W2   = (const float*)d_in[17];
    const float* b2   = (const float*)d_in[18];
    const float* g_f  = (const float*)d_in[19];
    const float* b_f  = (const float*)d_in[20];
    float* out = (float*)d_out;

    float *psS,*psS2,*mean,*var;
    fp16 *qkv_h,*kv_h,*q_h,*ffn_h,*res1h,*res2h,*ffnp_h,*src_h,*catT_h,*catS_h,*att_h,*h1_h;
    fp16 *wqkv_t,*wq_s,*wkv_s,*wpt_h,*wps_h,*w1_h,*w2_h;
    cudaGetSymbolAddress((void**)&qkv_h,  g_qkv_h);
    cudaGetSymbolAddress((void**)&kv_h,   g_kv_h);
    cudaGetSymbolAddress((void**)&q_h,    g_q_h);
    cudaGetSymbolAddress((void**)&ffn_h,  g_ffn_h);
    cudaGetSymbolAddress((void**)&res1h,  g_res1h);
    cudaGetSymbolAddress((void**)&res2h,  g_res2h);
    cudaGetSymbolAddress((void**)&ffnp_h, g_ffnp_h);
    cudaGetSymbolAddress((void**)&psS,    g_psS);
    cudaGetSymbolAddress((void**)&psS2,   g_psS2);
    cudaGetSymbolAddress((void**)&mean,   g_mean);
    cudaGetSymbolAddress((void**)&var,    g_var);
    cudaGetSymbolAddress((void**)&src_h,  g_src_h);
    cudaGetSymbolAddress((void**)&catT_h, g_catT_h);
    cudaGetSymbolAddress((void**)&catS_h, g_catS_h);
    cudaGetSymbolAddress((void**)&att_h,  g_att_h);
    cudaGetSymbolAddress((void**)&h1_h,   g_h1_h);
    cudaGetSymbolAddress((void**)&wqkv_t, g_wqkv_t);
    cudaGetSymbolAddress((void**)&wq_s,   g_wq_s);
    cudaGetSymbolAddress((void**)&wkv_s,  g_wkv_s);
    cudaGetSymbolAddress((void**)&wpt_h,  g_wpt_h);
    cudaGetSymbolAddress((void**)&wps_h,  g_wps_h);
    cudaGetSymbolAddress((void**)&w1_h,   g_w1_h);
    cudaGetSymbolAddress((void**)&w2_h,   g_w2_h);

    cudaFuncSetAttribute(qkv_all,     cudaFuncAttributeMaxDynamicSharedMemorySize, TG_SMEM);
    cudaFuncSetAttribute(proj_merged, cudaFuncAttributeMaxDynamicSharedMemorySize, TG_SMEM);
    cudaFuncSetAttribute(ffn1_gemm,   cudaFuncAttributeMaxDynamicSharedMemorySize, TG_SMEM);
    cudaFuncSetAttribute(ffn2_gemm,   cudaFuncAttributeMaxDynamicSharedMemorySize, TG_SMEM);

    // ---- ONE prep launch ----
    prep_all<<<(int)((PREP_TOTAL + 255)/256), 256>>>(
        src, src_h, Wp_t, wpt_h, Wp_s, wps_h, W1, w1_h, W2, w2_h,
        Wq_t, Wk_t, Wv_t, wqkv_t, Wq_s, wq_s, Wk_s, Wv_s, wkv_s);

    // ---- all QKV-type GEMMs in one launch ----
    qkv_all<<<dim3(6, 30, 24), 128, TG_SMEM>>>(src_h, wqkv_t, wq_s, wkv_s, qkv_h, q_h, kv_h);

    // ---- both attentions in one launch ----
    attn_all<<<3072 + NTOK, 256>>>(qkv_h, q_h, kv_h, catT_h, catS_h);

    // ---- both projections (+bias +fp16 residual +BN stats, fp16 out) ----
    proj_merged<<<dim3(48, 30), 128, TG_SMEM>>>(catT_h, catS_h, wpt_h, wps_h,
                                                res1h, res2h, bp_t, bp_s, src_h, psS, psS2);

    // ---- BN stage2 for both branches ----
    bn_stats2<<<dim3(DDIM/256, 2), 256>>>(psS, psS2, mean, var);

    // ---- att_h = bn_t + bn_s ----
    combine_att<<<(NEL/4 + 255)/256, 256>>>(res1h, res2h, g_t, b_t, g_s, b_s,
                                            mean, var, att_h);

    // ---- FFN1 split-K=4 (fp16 partials) + reduce ----
    ffn1_gemm<<<dim3(2, 30, 4), 128, TG_SMEM>>>(att_h, w1_h, ffnp_h);
    ffn1_reduce<<<(int)(((long)NTOK*FFD/8 + 255)/256), 256>>>(ffnp_h, b1, h1_h);

    // ---- FFN2 (+bias +fp16 residual +BN stats, fp16 out) ----
    ffn2_gemm<<<dim3(24, 30), 128, TG_SMEM>>>(h1_h, w2_h, b2, att_h, ffn_h, psS, psS2);

    // ---- final BN ----
    bn_stats2<<<dim3(DDIM/256, 1), 256>>>(psS, psS2, mean + 2*DDIM, var + 2*DDIM);
    final_bn<<<(NEL/4 + 255)/256, 256>>>(ffn_h, g_f, b_f, mean + 2*DDIM, var + 2*DDIM, out);
}

// round 16
// speedup vs baseline: 1.2241x; 1.1808x over previous
#include <cuda_runtime.h>
#include <cuda_fp16.h>
#include <stdint.h>
#include <math.h>

#define BB   32
#define TT   120
#define JJ   24
#define EE   128
#define HH   8
#define DH   16
#define DDIM 3072
#define FFD  256
#define NTOK (BB*TT)            // 3840
#define NEL  (NTOK*DDIM)        // 11,796,480
#define NROWCH 30
#define WELEM (HH*JJ*DH*EE)     // 393216

typedef __half fp16;

// ===================== PTX helpers =====================
__device__ __forceinline__ uint32_t smem_u32(const void* p) {
    uint32_t a;
    asm("{ .reg .u64 t; cvta.to.shared.u64 t, %1; cvt.u32.u64 %0, t; }" : "=r"(a) : "l"(p));
    return a;
}
__device__ __forceinline__ void ldmx4(uint32_t* r, uint32_t addr) {
    asm volatile("ldmatrix.sync.aligned.m8n8.x4.shared.b16 {%0,%1,%2,%3}, [%4];"
        : "=r"(r[0]), "=r"(r[1]), "=r"(r[2]), "=r"(r[3]) : "r"(addr));
}
__device__ __forceinline__ void mma16816(float* c, const uint32_t* a, uint32_t b0, uint32_t b1) {
    asm volatile("mma.sync.aligned.m16n8k16.row.col.f32.f16.f16.f32 "
        "{%0,%1,%2,%3}, {%4,%5,%6,%7}, {%8,%9}, {%0,%1,%2,%3};"
        : "+f"(c[0]), "+f"(c[1]), "+f"(c[2]), "+f"(c[3])
        : "r"(a[0]), "r"(a[1]), "r"(a[2]), "r"(a[3]), "r"(b0), "r"(b1));
}
__device__ __forceinline__ void cpa16(uint32_t saddr, const void* g) {
    asm volatile("cp.async.ca.shared.global [%0], [%1], 16;" :: "r"(saddr), "l"(g));
}
#define CPA_COMMIT() asm volatile("cp.async.commit_group;" ::: "memory")
#define CPA_WAIT0()  asm volatile("cp.async.wait_group 0;" ::: "memory")

// ===================== scratch (device globals) =====================
__device__ __align__(16) fp16  g_qkv_h[NTOK*JJ*384];
__device__ __align__(16) fp16  g_kv_h [NTOK*JJ*256];
__device__ __align__(16) fp16  g_q_h  [NEL];
__device__ __align__(16) fp16  g_ffn_h[NEL];
__device__ __align__(16) fp16  g_res1h[NEL];
__device__ __align__(16) fp16  g_res2h[NEL];
__device__ __align__(16) fp16  g_ffnp_h[4*NTOK*FFD];
__device__ __align__(16) fp16 g_src_h[NEL];
__device__ __align__(16) fp16 g_catT_h[NEL];
__device__ __align__(16) fp16 g_catS_h[NEL];
__device__ __align__(16) fp16 g_att_h[NEL];
__device__ __align__(16) fp16 g_h1_h[NTOK*FFD];
__device__ __align__(16) fp16 g_wqkv_t[JJ*384*EE];
__device__ __align__(16) fp16 g_wq_s[WELEM];
__device__ __align__(16) fp16 g_wkv_s[2*HH*DH*EE];
__device__ __align__(16) fp16 g_wpt_h[DDIM*DDIM];
__device__ __align__(16) fp16 g_wps_h[DDIM*DDIM];
__device__ __align__(16) fp16 g_w1_h[FFD*DDIM];
__device__ __align__(16) fp16 g_w2_h[DDIM*FFD];
__device__ float g_psS [2*NROWCH*DDIM];
__device__ float g_psS2[2*NROWCH*DDIM];
__device__ float g_mean[3*DDIM];
__device__ float g_var [3*DDIM];

// ===================== ONE merged prep kernel =====================
#define SEG0 ((long)NEL/4)
#define SEG1 ((long)DDIM*DDIM/4)
#define SEG2 ((long)DDIM*DDIM/4)
#define SEG3 ((long)FFD*DDIM/4)
#define SEG4 ((long)FFD*DDIM/4)
#define CVT_TOTAL (SEG0 + SEG1 + SEG2 + SEG3 + SEG4)
#define PREP_TOTAL (CVT_TOTAL + 2L*WELEM + (long)HH*DH*EE)
__global__ __launch_bounds__(256) void prep_all(
    const float* __restrict__ src,  fp16* __restrict__ src_h,
    const float* __restrict__ wpt,  fp16* __restrict__ wpt_h,
    const float* __restrict__ wps,  fp16* __restrict__ wps_h,
    const float* __restrict__ w1,   fp16* __restrict__ w1_h,
    const float* __restrict__ w2,   fp16* __restrict__ w2_h,
    const float* __restrict__ wq_t, const float* __restrict__ wk_t,
    const float* __restrict__ wv_t, fp16* __restrict__ wqkv_t,
    const float* __restrict__ wqs,  fp16* __restrict__ wq_s,
    const float* __restrict__ wks,  const float* __restrict__ wvs,
    fp16* __restrict__ wkv_s)
{
    long i = (long)blockIdx.x*256 + threadIdx.x;
    if (i >= PREP_TOTAL) return;
    if (i < CVT_TOTAL) {
        const float* in; fp16* o; long k;
        if      (i < SEG0)                  { in = src; o = src_h; k = i; }
        else if (i < SEG0+SEG1)             { in = wpt; o = wpt_h; k = i - SEG0; }
        else if (i < SEG0+SEG1+SEG2)        { in = wps; o = wps_h; k = i - SEG0 - SEG1; }
        else if (i < SEG0+SEG1+SEG2+SEG3)   { in = w1;  o = w1_h;  k = i - SEG0 - SEG1 - SEG2; }
        else                                { in = w2;  o = w2_h;  k = i - SEG0 - SEG1 - SEG2 - SEG3; }
        float4 x = ((const float4*)in)[k];
        ((__half2*)o)[2*k]   = __floats2half2_rn(x.x, x.y);
        ((__half2*)o)[2*k+1] = __floats2half2_rn(x.z, x.w);
        return;
    }
    long j = i - CVT_TOTAL;
    if (j < WELEM) {
        int idx = (int)j;
        int e  = idx & 127;
        int r  = idx >> 7;
        int dd = r & 15;
        int hj = r >> 4;
        int jj = hj % JJ;
        int h  = hj / JJ;
        int ob = jj*(384*128) + (h*16 + dd)*128 + e;
        wqkv_t[ob          ] = __float2half_rn(wq_t[idx]);
        wqkv_t[ob + 128*128] = __float2half_rn(wk_t[idx]);
        wqkv_t[ob + 256*128] = __float2half_rn(wv_t[idx]);
        return;
    }
    j -= WELEM;
    if (j < WELEM) {
        int idx = (int)j;
        int e  = idx & 127;
        int r  = idx >> 7;
        int dd = r & 15;
        int hj = r >> 4;
        int jj = hj % JJ;
        int h  = hj / JJ;
        wq_s[jj*16384 + (h*16 + dd)*128 + e] = __float2half_rn(wqs[idx]);
        return;
    }
    {
        int idx = (int)(j - WELEM);
        int n = HH*DH*EE;
        wkv_s[idx]     = __float2half_rn(wks[idx]);
        wkv_s[idx + n] = __float2half_rn(wvs[idx]);
    }
}

// ===================== GEMM body: CTA 128x128, 4 warps x (64x64), BK=64, 2-stage =====================
#define ROWB 144
#define ABYTES (128*ROWB)
#define BUFBYTES (2*ABYTES)   // 36864 per stage
#define TG_SMEM (2*BUFBYTES)  // 73728 -> 2 CTAs/SM
template<bool STATS, bool OUTH, bool RESH>
__device__ __forceinline__ void gemm_body(
    const fp16* __restrict__ Ab, long lda,
    const fp16* __restrict__ Bb, long ldb,
    float* __restrict__ Cf, fp16* __restrict__ Ch, long ldc,
    const float* __restrict__ bias,
    const fp16* __restrict__ resh, long ldres,
    int K, int relu,
    float* __restrict__ psS, float* __restrict__ ps2S,
    char* dsm)
{
    const uint32_t sbase = smem_u32(dsm);
    const int tid = threadIdx.x;
    const int wid = tid >> 5, lid = tid & 31;
    const int wm = wid & 1, wn = wid >> 1;      // 2x2 warp grid, 64x64 each

    float acc[4][8][4];
    #pragma unroll
    for (int mt = 0; mt < 4; mt++)
        #pragma unroll
        for (int nt = 0; nt < 8; nt++)
            #pragma unroll
            for (int c = 0; c < 4; c++) acc[mt][nt][c] = 0.f;

    const int NC = K >> 6;
    const int row = tid >> 3;          // 0..15
    const int g   = tid & 7;
    const uint32_t so = (uint32_t)(row*ROWB + g*16);

    // running global pointers (advance by 64 halves per chunk; no per-chunk IMAD.WIDE)
    const fp16* aP = Ab + (long)row*lda + g*8;
    const fp16* bP = Bb + (long)row*ldb + g*8;
    const long a16 = 16*lda, b16 = 16*ldb;

    // prefetch chunk 0 -> buf 0
    {
        uint32_t sA0 = sbase, sB0 = sbase + ABYTES;
        #pragma unroll
        for (int i = 0; i < 8; i++) {
            uint32_t s2 = so + (uint32_t)(i*16*ROWB);
            cpa16(sA0 + s2, aP + i*a16);
            cpa16(sB0 + s2, bP + i*b16);
        }
        CPA_COMMIT();
        aP += 64; bP += 64;
    }

    for (int kc = 0; kc < NC; kc++) {
        const int b = kc & 1;
        CPA_WAIT0();
        __syncthreads();

        if (kc + 1 < NC) {
            uint32_t sA0 = sbase + (b^1)*BUFBYTES, sB0 = sA0 + ABYTES;
            #pragma unroll
            for (int i = 0; i < 8; i++) {
                uint32_t s2 = so + (uint32_t)(i*16*ROWB);
                cpa16(sA0 + s2, aP + i*a16);
                cpa16(sB0 + s2, bP + i*b16);
            }
            CPA_COMMIT();
            aP += 64; bP += 64;
        }

        const uint32_t sA0 = sbase + b*BUFBYTES, sB0 = sA0 + ABYTES;
        const int fr = lid & 15;
        #pragma unroll
        for (int kk = 0; kk < 4; kk++) {
            const uint32_t fcb = (uint32_t)((kk*16 + (lid >> 4)*8) * 2);
            uint32_t af[4][4];
            uint32_t bf[4][4];
            #pragma unroll
            for (int mt = 0; mt < 4; mt++)
                ldmx4(af[mt], sA0 + (uint32_t)((wm*64 + mt*16 + fr)*ROWB) + fcb);
            #pragma unroll
            for (int p = 0; p < 4; p++)
                ldmx4(bf[p], sB0 + (uint32_t)((wn*64 + p*16 + fr)*ROWB) + fcb);
            #pragma unroll
            for (int p = 0; p < 4; p++) {
                #pragma unroll
                for (int mt = 0; mt < 4; mt++) {
                    mma16816(acc[mt][2*p+0], af[mt], bf[p][0], bf[p][2]);
                    mma16816(acc[mt][2*p+1], af[mt], bf[p][1], bf[p][3]);
                }
            }
        }
    }

    // ---- epilogue ----
    const int qr = lid >> 2;
    const int qc = (lid & 3) * 2;
    float colS[16], colS2[16];
    if (STATS) {
        #pragma unroll
        for (int i = 0; i < 16; i++) { colS[i] = 0.f; colS2[i] = 0.f; }
    }
    #pragma unroll
    for (int mt = 0; mt < 4; mt++) {
        #pragma unroll
        for (int half = 0; half < 2; half++) {
            int m = wm*64 + mt*16 + half*8 + qr;
            #pragma unroll
            for (int nt = 0; nt < 8; nt++) {
                int n = wn*64 + nt*8 + qc;
                float v0 = acc[mt][nt][half*2+0];
                float v1 = acc[mt][nt][half*2+1];
                if (bias) { v0 += bias[n]; v1 += bias[n+1]; }
                if (RESH) {
                    __half2 rh = *(const __half2*)(resh + (long)m*ldres + n);
                    float2 rf = __half22float2(rh);
                    v0 += rf.x; v1 += rf.y;
                }
                if (relu) { v0 = fmaxf(v0, 0.f); v1 = fmaxf(v1, 0.f); }
                if (OUTH) {
                    *(__half2*)(Ch + (long)m*ldc + n) = __floats2half2_rn(v0, v1);
                } else {
                    float* Cp = Cf + (long)m*ldc + n;
                    Cp[0] = v0; Cp[1] = v1;
                }
                if (STATS) {
                    colS [nt*2+0] += v0; colS2[nt*2+0] += v0*v0;
                    colS [nt*2+1] += v1; colS2[nt*2+1] += v1*v1;
                }
            }
        }
    }
    if (STATS) {
        #pragma unroll
        for (int i = 0; i < 16; i++) {
            float s = colS[i], s2 = colS2[i];
            #pragma unroll
            for (int o = 4; o < 32; o <<= 1) {
                s  += __shfl_xor_sync(0xFFFFFFFFu, s,  o);
                s2 += __shfl_xor_sync(0xFFFFFFFFu, s2, o);
            }
            colS[i] = s; colS2[i] = s2;
        }
        __syncthreads();
        float* sred = (float*)dsm;   // [2 types][2 wm][128 cols]
        if (qr == 0) {
            int q2 = lid;  // 0..3
            #pragma unroll
            for (int i = 0; i < 16; i++) {
                int col = wn*64 + (i>>1)*8 + q2*2 + (i&1);
                sred[(0*2 + wm)*128 + col] = colS[i];
                sred[(1*2 + wm)*128 + col] = colS2[i];
            }
        }
        __syncthreads();
        #pragma unroll
        for (int rep = 0; rep < 2; rep++) {
            int s   = tid + rep*128;
            int ty  = s >> 7;
            int col = s & 127;
            float v = sred[(ty*2 + 0)*128 + col] + sred[(ty*2 + 1)*128 + col];
            if (ty == 0) psS[col] = v; else ps2S[col] = v;
        }
    }
}

// ---- merged QKV-type GEMMs: grid (6, 30, 24), 128 threads ----
__global__ __launch_bounds__(128, 2) void qkv_all(
    const fp16* __restrict__ src_h, const fp16* __restrict__ wqkv,
    const fp16* __restrict__ wqs, const fp16* __restrict__ wkvs,
    fp16* qkv_h, fp16* q_h, fp16* kv_h)
{
    extern __shared__ char dsm[];
    int bx = blockIdx.x, by = blockIdx.y, bz = blockIdx.z;
    const fp16 *A, *B; fp16* Ch; long lda, ldc;
    if (bx < 3) {
        A  = src_h + (long)bz*128 + (long)by*128*DDIM; lda = DDIM;
        B  = wqkv + (long)bz*(384*128) + (long)bx*128*128;
        Ch = qkv_h + (long)by*128*9216 + (long)bz*384 + bx*128; ldc = 9216;
    } else if (bx == 3) {
        A  = src_h + (long)bz*128 + (long)by*128*DDIM; lda = DDIM;
        B  = wqs + (long)bz*16384;
        Ch = q_h + (long)by*128*DDIM + (long)bz*128; ldc = DDIM;
    } else {
        long rt = (long)bz*30 + by;
        A  = src_h + rt*128*EE; lda = EE;
        B  = wkvs + (long)(bx-4)*128*EE;
        Ch = kv_h + rt*128*256 + (long)(bx-4)*128; ldc = 256;
    }
    gemm_body<false, true, false>(A, lda, B, EE, nullptr, Ch, ldc,
                                  nullptr, nullptr, 0, EE, 0, nullptr, nullptr, dsm);
}

// ---- merged projections (fp16 out + fp16 residual(src_h) + BN stats): grid (48, 30) ----
__global__ __launch_bounds__(128, 2) void proj_merged(
    const fp16* __restrict__ catT, const fp16* __restrict__ catS,
    const fp16* __restrict__ wpt, const fp16* __restrict__ wps,
    fp16* res1h, fp16* res2h,
    const float* __restrict__ bpt, const float* __restrict__ bps,
    const fp16* __restrict__ src_h,
    float* psS, float* psS2)
{
    extern __shared__ char dsm[];
    int bx = blockIdx.x, by = blockIdx.y;
    int sp = bx >= 24;
    int nx = sp ? bx - 24 : bx;
    const fp16* A = (sp ? catS : catT) + (long)by*128*DDIM;
    const fp16* B = (sp ? wps : wpt) + (long)nx*128*DDIM;
    fp16* C = (sp ? res2h : res1h) + (long)by*128*DDIM + nx*128;
    const float* bias = (sp ? bps : bpt) + nx*128;
    const fp16* resh = src_h + (long)by*128*DDIM + nx*128;
    float* pS  = psS  + (long)sp*NROWCH*DDIM + (long)by*DDIM + nx*128;
    float* pS2 = psS2 + (long)sp*NROWCH*DDIM + (long)by*DDIM + nx*128;
    gemm_body<true, true, true>(A, DDIM, B, DDIM, nullptr, C, DDIM,
                                bias, resh, DDIM, DDIM, 0, pS, pS2, dsm);
}

// ---- FFN1 split-K: grid (2, 30, 4), fp16 partials ----
__global__ __launch_bounds__(128, 2) void ffn1_gemm(
    const fp16* __restrict__ att_h, const fp16* __restrict__ w1, fp16* ffnp_h)
{
    extern __shared__ char dsm[];
    int bx = blockIdx.x, by = blockIdx.y, bz = blockIdx.z;
    const fp16* A = att_h + (long)bz*768 + (long)by*128*DDIM;
    const fp16* B = w1 + (long)bx*128*DDIM + (long)bz*768;
    fp16* C = ffnp_h + (long)bz*((long)NTOK*FFD) + (long)by*128*FFD + bx*128;
    gemm_body<false, true, false>(A, DDIM, B, DDIM, nullptr, C, FFD,
                                  nullptr, nullptr, 0, 768, 0, nullptr, nullptr, dsm);
}

// ---- FFN2 + bias + fp16 residual(att_h) + BN stats, fp16 out: grid (24, 30) ----
__global__ __launch_bounds__(128, 2) void ffn2_gemm(
    const fp16* __restrict__ h1, const fp16* __restrict__ w2,
    const float* __restrict__ b2, const fp16* __restrict__ att_h,
    fp16* ffn_h, float* psS, float* psS2)
{
    extern __shared__ char dsm[];
    int bx = blockIdx.x, by = blockIdx.y;
    const fp16* A = h1 + (long)by*128*FFD;
    const fp16* B = w2 + (long)bx*128*FFD;
    fp16* C = ffn_h + (long)by*128*DDIM + bx*128;
    const float* bias = b2 + bx*128;
    const fp16* resh = att_h + (long)by*128*DDIM + bx*128;
    float* pS  = psS  + (long)by*DDIM + bx*128;
    float* pS2 = psS2 + (long)by*DDIM + bx*128;
    gemm_body<true, true, true>(A, FFD, B, FFD, nullptr, C, DDIM,
                                bias, resh, DDIM, FFD, 0, pS, pS2, dsm);
}

// ===================== merged attention (vectorized uint4 I/O) =====================
__global__ __launch_bounds__(256) void attn_all(
    const fp16* __restrict__ qkv, const fp16* __restrict__ q,
    const fp16* __restrict__ kv, fp16* __restrict__ oT, fp16* __restrict__ oS)
{
    __shared__ float sm[7680];
    int bi = blockIdx.x;
    if (bi < 3072) {
        int j = bi % 24, hp = (bi/24) & 3, b = bi / 96;
        int half = threadIdx.x >> 7;
        int tid = threadIdx.x & 127;
        int h = hp*2 + half;
        float* Ks = sm + half*(2*TT*DH);
        float* Vs = Ks + TT*DH;
        // vector loads: 240 groups of 8 halves for K and V each
        for (int idx = tid; idx < TT*2; idx += 128) {
            int t = idx >> 1, gg = idx & 1;
            long off = (long)(b*TT + t)*9216 + j*384 + h*DH + gg*8;
            uint4 k4 = *(const uint4*)(qkv + off + 128);
            uint4 v4 = *(const uint4*)(qkv + off + 256);
            float* kd = Ks + t*DH + gg*8;
            float* vd = Vs + t*DH + gg*8;
            const __half2* kh = (const __half2*)&k4;
            const __half2* vh = (const __half2*)&v4;
            #pragma unroll
            for (int u = 0; u < 4; u++) {
                float2 fk = __half22float2(kh[u]);
                float2 fv = __half22float2(vh[u]);
                kd[2*u] = fk.x; kd[2*u+1] = fk.y;
                vd[2*u] = fv.x; vd[2*u+1] = fv.y;
            }
        }
        __syncthreads();
        int t = tid;
        if (t < TT) {
            float qr[DH];
            long qoff = (long)(b*TT + t)*9216 + j*384 + h*DH;
            {
                uint4 q0 = *(const uint4*)(qkv + qoff);
                uint4 q1 = *(const uint4*)(qkv + qoff + 8);
                const __half2* qh0 = (const __half2*)&q0;
                const __half2* qh1 = (const __half2*)&q1;
                #pragma unroll
                for (int u = 0; u < 4; u++) {
                    float2 f0 = __half22float2(qh0[u]);
                    float2 f1 = __half22float2(qh1[u]);
                    qr[2*u]     = f0.x; qr[2*u+1]     = f0.y;
                    qr[8+2*u]   = f1.x; qr[8+2*u+1]   = f1.y;
                }
            }
            float m = -1e30f, l = 0.f, acc[DH];
            #pragma unroll
            for (int dd = 0; dd < DH; dd++) acc[dd] = 0.f;
            for (int s = 0; s <= t; s++) {
                float sc = 0.f;
                #pragma unroll
                for (int dd = 0; dd < DH; dd++) sc = fmaf(qr[dd], Ks[s*DH + dd], sc);
                sc *= 0.25f;
                float mn = fmaxf(m, sc);
                float corr = __expf(m - mn);
                float p    = __expf(sc - mn);
                l = l*corr + p;
                #pragma unroll
                for (int dd = 0; dd < DH; dd++) acc[dd] = fmaf(acc[dd], corr, p*Vs[s*DH + dd]);
                m = mn;
            }
            float inv = 1.f / l;
            long ooff = (long)(b*TT + t)*DDIM + h*(JJ*DH) + j*DH;
            uint32_t ow[8];
            #pragma unroll
            for (int u = 0; u < 8; u++) {
                __half2 hh = __floats2half2_rn(acc[2*u]*inv, acc[2*u+1]*inv);
                ow[u] = *(uint32_t*)&hh;
            }
            *(uint4*)(oT + ooff)     = make_uint4(ow[0], ow[1], ow[2], ow[3]);
            *(uint4*)(oT + ooff + 8) = make_uint4(ow[4], ow[5], ow[6], ow[7]);
        }
    } else {
        int tok  = bi - 3072;
        int h    = threadIdx.x >> 5;
        int lane = threadIdx.x & 31;
        float* Ks = sm;
        float* Vs = sm + HH*JJ*DH;
        for (int idx = lane; idx < JJ*2; idx += 32) {
            int jj = idx >> 1, gg = idx & 1;
            long off = ((long)tok*JJ + jj)*256 + h*DH + gg*8;
            uint4 k4 = *(const uint4*)(kv + off);
            uint4 v4 = *(const uint4*)(kv + off + 128);
            float* kd = Ks + (h*JJ + jj)*DH + gg*8;
            float* vd = Vs + (h*JJ + jj)*DH + gg*8;
            const __half2* kh = (const __half2*)&k4;
            const __half2* vh = (const __half2*)&v4;
            #pragma unroll
            for (int u = 0; u < 4; u++) {
                float2 fk = __half22float2(kh[u]);
                float2 fv = __half22float2(vh[u]);
                kd[2*u] = fk.x; kd[2*u+1] = fk.y;
                vd[2*u] = fv.x; vd[2*u+1] = fv.y;
            }
        }
        __syncwarp();
        if (lane < JJ) {
            int j = lane;
            float qr[DH];
            long qoff = (long)tok*DDIM + j*128 + h*DH;
            {
                uint4 q0 = *(const uint4*)(q + qoff);
                uint4 q1 = *(const uint4*)(q + qoff + 8);
                const __half2* qh0 = (const __half2*)&q0;
                const __half2* qh1 = (const __half2*)&q1;
                #pragma unroll
                for (int u = 0; u < 4; u++) {
                    float2 f0 = __half22float2(qh0[u]);
                    float2 f1 = __half22float2(qh1[u]);
                    qr[2*u]     = f0.x; qr[2*u+1]     = f0.y;
                    qr[8+2*u]   = f1.x; qr[8+2*u+1]   = f1.y;
                }
            }
            float s[JJ];
            float m = -1e30f;
            #pragma unroll
            for (int kk = 0; kk < JJ; kk++) {
                float sc = 0.f;
                #pragma unroll
                for (int dd = 0; dd < DH; dd++) sc = fmaf(qr[dd], Ks[(h*JJ + kk)*DH + dd], sc);
                sc *= 0.25f;
                s[kk] = sc;
                m = fmaxf(m, sc);
            }
            float l = 0.f;
            #pragma unroll
            for (int kk = 0; kk < JJ; kk++) { s[kk] = __expf(s[kk] - m); l += s[kk]; }
            float acc[DH];
            #pragma unroll
            for (int dd = 0; dd < DH; dd++) acc[dd] = 0.f;
            #pragma unroll
            for (int kk = 0; kk < JJ; kk++)
                #pragma unroll
                for (int dd = 0; dd < DH; dd++) acc[dd] = fmaf(s[kk], Vs[(h*JJ + kk)*DH + dd], acc[dd]);
            float inv = 1.f / l;
            long ooff = (long)tok*DDIM + h*(JJ*DH) + j*DH;
            uint32_t ow[8];
            #pragma unroll
            for (int u = 0; u < 8; u++) {
                __half2 hh = __floats2half2_rn(acc[2*u]*inv, acc[2*u+1]*inv);
                ow[u] = *(uint32_t*)&hh;
            }
            *(uint4*)(oS + ooff)     = make_uint4(ow[0], ow[1], ow[2], ow[3]);
            *(uint4*)(oS + ooff + 8) = make_uint4(ow[4], ow[5], ow[6], ow[7]);
        }
    }
}

// ===================== FFN1 split-K reduce (fp16 partials) =====================
__global__ __launch_bounds__(256) void ffn1_reduce(
    const fp16* __restrict__ p, const float* __restrict__ b1, fp16* __restrict__ oh)
{
    long i = (long)blockIdx.x*256 + threadIdx.x;      // over NTOK*FFD/8
    if (i >= (long)NTOK*FFD/8) return;
    const long stride = (long)NTOK*FFD/8;
    uint4 pa = ((const uint4*)p)[i];
    uint4 pb = ((const uint4*)p)[i + stride];
    uint4 pc = ((const uint4*)p)[i + 2*stride];
    uint4 pd = ((const uint4*)p)[i + 3*stride];
    int c0 = (int)((i*8) % FFD);
    uint32_t ra[4] = {pa.x, pa.y, pa.z, pa.w};
    uint32_t rb[4] = {pb.x, pb.y, pb.z, pb.w};
    uint32_t rc[4] = {pc.x, pc.y, pc.z, pc.w};
    uint32_t rd[4] = {pd.x, pd.y, pd.z, pd.w};
    uint32_t ro[4];
    #pragma unroll
    for (int k = 0; k < 4; k++) {
        float2 fa = __half22float2(*(__half2*)&ra[k]);
        float2 fb = __half22float2(*(__half2*)&rb[k]);
        float2 fc = __half22float2(*(__half2*)&rc[k]);
        float2 fd = __half22float2(*(__half2*)&rd[k]);
        float v0 = fmaxf(fa.x + fb.x + fc.x + fd.x + b1[c0 + 2*k],     0.f);
        float v1 = fmaxf(fa.y + fb.y + fc.y + fd.y + b1[c0 + 2*k + 1], 0.f);
        __half2 h = __floats2half2_rn(v0, v1);
        ro[k] = *(uint32_t*)&h;
    }
    ((uint4*)oh)[i] = make_uint4(ro[0], ro[1], ro[2], ro[3]);
}

// ===================== BN stage 2 =====================
__global__ __launch_bounds__(256) void bn_stats2(
    const float* __restrict__ ps, const float* __restrict__ ps2,
    float* __restrict__ mean, float* __restrict__ var)
{
    int c = blockIdx.x*256 + threadIdx.x;
    long base = (long)blockIdx.y*NROWCH*DDIM;
    float s = 0.f, s2 = 0.f;
    #pragma unroll
    for (int r = 0; r < NROWCH; r++) { s += ps[base + (long)r*DDIM + c]; s2 += ps2[base + (long)r*DDIM + c]; }
    float m = s / (float)NTOK;
    mean[blockIdx.y*DDIM + c] = m;
    var [blockIdx.y*DDIM + c] = s2 / (float)NTOK - m*m;
}

// att_h = bn_t(res1h) + bn_s(res2h)
__global__ __launch_bounds__(256) void combine_att(
    const fp16* __restrict__ x1, const fp16* __restrict__ x2,
    const float* __restrict__ gt, const float* __restrict__ bt,
    const float* __restrict__ gs, const float* __restrict__ bs,
    const float* __restrict__ mean, const float* __restrict__ var,
    fp16* __restrict__ oh)
{
    long i = (long)blockIdx.x*256 + threadIdx.x;
    if (i >= NEL/4) return;
    int c0 = (int)((i*4) % DDIM);
    float2 a01 = __half22float2(((const __half2*)x1)[2*i]);
    float2 a23 = __half22float2(((const __half2*)x1)[2*i+1]);
    float2 b01 = __half22float2(((const __half2*)x2)[2*i]);
    float2 b23 = __half22float2(((const __half2*)x2)[2*i+1]);
    float xa[4] = {a01.x, a01.y, a23.x, a23.y};
    float xb[4] = {b01.x, b01.y, b23.x, b23.y};
    float r[4];
    #pragma unroll
    for (int k = 0; k < 4; k++) {
        int c = c0 + k;
        float va = (xa[k] - mean[c])        * rsqrtf(var[c]        + 1e-5f) * gt[c] + bt[c];
        float vb = (xb[k] - mean[DDIM + c]) * rsqrtf(var[DDIM + c] + 1e-5f) * gs[c] + bs[c];
        r[k] = va + vb;
    }
    ((__half2*)oh)[2*i]   = __floats2half2_rn(r[0], r[1]);
    ((__half2*)oh)[2*i+1] = __floats2half2_rn(r[2], r[3]);
}

// final BN reads fp16 ffn
__global__ __launch_bounds__(256) void final_bn(
    const fp16* __restrict__ x,
    const float* __restrict__ gf, const float* __restrict__ bf,
    const float* __restrict__ mean, const float* __restrict__ var,
    float* __restrict__ out)
{
    long i = (long)blockIdx.x*256 + threadIdx.x;
    if (i >= NEL/4) return;
    int c0 = (int)((i*4) % DDIM);
    float2 a01 = __half22float2(((const __half2*)x)[2*i]);
    float2 a23 = __half22float2(((const __half2*)x)[2*i+1]);
    float xa[4] = {a01.x, a01.y, a23.x, a23.y};
    float r[4];
    #pragma unroll
    for (int k = 0; k < 4; k++) {
        int c = c0 + k;
        r[k] = (xa[k] - mean[c]) * rsqrtf(var[c] + 1e-5f) * gf[c] + bf[c];
    }
    ((float4*)out)[i] = make_float4(r[0], r[1], r[2], r[3]);
}

// ===================== launch =====================
extern "C" void kernel_launch(void* const* d_in, const int* in_sizes, int n_in,
                              void* d_out, int out_size)
{
    const float* src  = (const float*)d_in[0];
    const float* Wq_t = (const float*)d_in[1];
    const float* Wk_t = (const float*)d_in[2];
    const float* Wv_t = (const float*)d_in[3];
    const float* Wp_t = (const float*)d_in[4];
    const float* bp_t = (const float*)d_in[5];
    const float* g_t  = (const float*)d_in[6];
    const float* b_t  = (const float*)d_in[7];
    const float* Wq_s = (const float*)d_in[8];
    const float* Wk_s = (const float*)d_in[9];
    const float* Wv_s = (const float*)d_in[10];
    const float* Wp_s = (const float*)d_in[11];
    const float* bp_s = (const float*)d_in[12];
    const float* g_s  = (const float*)d_in[13];
    const float* b_s  = (const float*)d_in[14];
    const float* W1   = (const float*)d_in[15];
    const float* b1   = (const float*)d_in[16];
    const float* W2   = (const float*)d_in[17];
    const float* b2   = (const float*)d_in[18];
    const float* g_f  = (const float*)d_in[19];
    const float* b_f  = (const float*)d_in[20];
    float* out = (float*)d_out;

    float *psS,*psS2,*mean,*var;
    fp16 *qkv_h,*kv_h,*q_h,*ffn_h,*res1h,*res2h,*ffnp_h,*src_h,*catT_h,*catS_h,*att_h,*h1_h;
    fp16 *wqkv_t,*wq_s,*wkv_s,*wpt_h,*wps_h,*w1_h,*w2_h;
    cudaGetSymbolAddress((void**)&qkv_h,  g_qkv_h);
    cudaGetSymbolAddress((void**)&kv_h,   g_kv_h);
    cudaGetSymbolAddress((void**)&q_h,    g_q_h);
    cudaGetSymbolAddress((void**)&ffn_h,  g_ffn_h);
    cudaGetSymbolAddress((void**)&res1h,  g_res1h);
    cudaGetSymbolAddress((void**)&res2h,  g_res2h);
    cudaGetSymbolAddress((void**)&ffnp_h, g_ffnp_h);
    cudaGetSymbolAddress((void**)&psS,    g_psS);
    cudaGetSymbolAddress((void**)&psS2,   g_psS2);
    cudaGetSymbolAddress((void**)&mean,   g_mean);
    cudaGetSymbolAddress((void**)&var,    g_var);
    cudaGetSymbolAddress((void**)&src_h,  g_src_h);
    cudaGetSymbolAddress((void**)&catT_h, g_catT_h);
    cudaGetSymbolAddress((void**)&catS_h, g_catS_h);
    cudaGetSymbolAddress((void**)&att_h,  g_att_h);
    cudaGetSymbolAddress((void**)&h1_h,   g_h1_h);
    cudaGetSymbolAddress((void**)&wqkv_t, g_wqkv_t);
    cudaGetSymbolAddress((void**)&wq_s,   g_wq_s);
    cudaGetSymbolAddress((void**)&wkv_s,  g_wkv_s);
    cudaGetSymbolAddress((void**)&wpt_h,  g_wpt_h);
    cudaGetSymbolAddress((void**)&wps_h,  g_wps_h);
    cudaGetSymbolAddress((void**)&w1_h,   g_w1_h);
    cudaGetSymbolAddress((void**)&w2_h,   g_w2_h);

    cudaFuncSetAttribute(qkv_all,     cudaFuncAttributeMaxDynamicSharedMemorySize, TG_SMEM);
    cudaFuncSetAttribute(proj_merged, cudaFuncAttributeMaxDynamicSharedMemorySize, TG_SMEM);
    cudaFuncSetAttribute(ffn1_gemm,   cudaFuncAttributeMaxDynamicSharedMemorySize, TG_SMEM);
    cudaFuncSetAttribute(ffn2_gemm,   cudaFuncAttributeMaxDynamicSharedMemorySize, TG_SMEM);

    // ---- ONE prep launch ----
    prep_all<<<(int)((PREP_TOTAL + 255)/256), 256>>>(
        src, src_h, Wp_t, wpt_h, Wp_s, wps_h, W1, w1_h, W2, w2_h,
        Wq_t, Wk_t, Wv_t, wqkv_t, Wq_s, wq_s, Wk_s, Wv_s, wkv_s);

    // ---- all QKV-type GEMMs in one launch ----
    qkv_all<<<dim3(6, 30, 24), 128, TG_SMEM>>>(src_h, wqkv_t, wq_s, wkv_s, qkv_h, q_h, kv_h);

    // ---- both attentions in one launch ----
    attn_all<<<3072 + NTOK, 256>>>(qkv_h, q_h, kv_h, catT_h, catS_h);

    // ---- both projections (+bias +fp16 residual +BN stats, fp16 out) ----
    proj_merged<<<dim3(48, 30), 128, TG_SMEM>>>(catT_h, catS_h, wpt_h, wps_h,
                                                res1h, res2h, bp_t, bp_s, src_h, psS, psS2);

    // ---- BN stage2 for both branches ----
    bn_stats2<<<dim3(DDIM/256, 2), 256>>>(psS, psS2, mean, var);

    // ---- att_h = bn_t + bn_s ----
    combine_att<<<(NEL/4 + 255)/256, 256>>>(res1h, res2h, g_t, b_t, g_s, b_s,
                                            mean, var, att_h);

    // ---- FFN1 split-K=4 (fp16 partials) + reduce ----
    ffn1_gemm<<<dim3(2, 30, 4), 128, TG_SMEM>>>(att_h, w1_h, ffnp_h);
    ffn1_reduce<<<(int)(((long)NTOK*FFD/8 + 255)/256), 256>>>(ffnp_h, b1, h1_h);

    // ---- FFN2 (+bias +fp16 residual +BN stats, fp16 out) ----
    ffn2_gemm<<<dim3(24, 30), 128, TG_SMEM>>>(h1_h, w2_h, b2, att_h, ffn_h, psS, psS2);

    // ---- final BN ----
    bn_stats2<<<dim3(DDIM/256, 1), 256>>>(psS, psS2, mean + 2*DDIM, var + 2*DDIM);
    final_bn<<<(NEL/4 + 255)/256, 256>>>(ffn_h, g_f, b_f, mean + 2*DDIM, var + 2*DDIM, out);
}